// round 3
// baseline (speedup 1.0000x reference)
#include <cuda_runtime.h>

// ----------------------------------------------------------------------------
// TGAT edge classifier, restructured:
//   p[n] = h_nodes[n] @ Wm1[0:64]      (node stage)
//   q[n] = h_nodes[n] @ Wm1[64:128]    (node stage)
//   Wz   = [ We @ Wm1[128:192] ; Wm1[192:224] ]   (64x64, prep stage)
//   bc   = bm1 + be @ Wm1[128:192]
//   hidden_e = [ea_e | te_e] @ Wz + p[src_e] + q[dst_e] + bc
//   out_e    = relu(hidden_e) . Wm2 + bm2
//
// R3: packed fma.rn.f32x2 inner loops (2 lane-FMAs per issue slot on the fma
// pipe vs 1 for 3-reg FFMA), parallelized prep kernel.
// ----------------------------------------------------------------------------

#define N_CAP 100000
#define H 64

typedef unsigned long long u64;

__device__ float g_p[N_CAP * H];
__device__ float g_q[N_CAP * H];
__device__ float g_Wz[H * H];
__device__ float g_bc[H];

// ---------------------------------------------------- packed f32x2 helpers --
__device__ __forceinline__ u64 pack2(float a) {
    u64 r;
    asm("mov.b64 %0, {%1, %1};" : "=l"(r) : "f"(a));
    return r;
}
__device__ __forceinline__ void fma2(u64& d, u64 a, u64 b) {
    asm("fma.rn.f32x2 %0, %1, %2, %0;" : "+l"(d) : "l"(a), "l"(b));
}
__device__ __forceinline__ float2 unpack2(u64 v) {
    float2 f;
    asm("mov.b64 {%0, %1}, %2;" : "=f"(f.x), "=f"(f.y) : "l"(v));
    return f;
}

struct AccP { u64 v[8]; };  // 16 packed fp32 accumulators

// acc(16 outputs, tile jt) += zrow(64) @ W(64x64) column tile  [packed]
__device__ __forceinline__ void tile_gemm2(const float* __restrict__ zrow,
                                           const float* __restrict__ wbase,
                                           int jt, AccP& A) {
#pragma unroll 8
    for (int k = 0; k < 64; ++k) {
        u64 zz = pack2(zrow[k]);
        const ulonglong2* w =
            reinterpret_cast<const ulonglong2*>(wbase + k * 64 + jt * 16);
        ulonglong2 w0 = w[0], w1 = w[1], w2 = w[2], w3 = w[3];
        fma2(A.v[0], zz, w0.x); fma2(A.v[1], zz, w0.y);
        fma2(A.v[2], zz, w1.x); fma2(A.v[3], zz, w1.y);
        fma2(A.v[4], zz, w2.x); fma2(A.v[5], zz, w2.y);
        fma2(A.v[6], zz, w3.x); fma2(A.v[7], zz, w3.y);
    }
}

// hout(64 regs) = relu(zrow @ W + b)
__device__ __forceinline__ void layer_relu2(const float* __restrict__ zrow,
                                            const float* __restrict__ W,
                                            const float* __restrict__ b,
                                            float* __restrict__ hout) {
#pragma unroll
    for (int jt = 0; jt < 4; ++jt) {
        const u64* bb = reinterpret_cast<const u64*>(b) + jt * 8;
        AccP A;
#pragma unroll
        for (int i = 0; i < 8; ++i) A.v[i] = bb[i];
        tile_gemm2(zrow, W, jt, A);
        float* o = hout + jt * 16;
#pragma unroll
        for (int i = 0; i < 8; ++i) {
            float2 f = unpack2(A.v[i]);
            o[2 * i]     = fmaxf(f.x, 0.f);
            o[2 * i + 1] = fmaxf(f.y, 0.f);
        }
    }
}

// dst = zrow @ W   (no bias, no relu); dst 16B-aligned gmem
__device__ __forceinline__ void proj_store2(const float* __restrict__ zrow,
                                            const float* __restrict__ W,
                                            u64* __restrict__ dst) {
#pragma unroll
    for (int jt = 0; jt < 4; ++jt) {
        AccP A;
#pragma unroll
        for (int i = 0; i < 8; ++i) A.v[i] = 0ull;  // {0.f, 0.f}
        tile_gemm2(zrow, W, jt, A);
        ulonglong2* d = reinterpret_cast<ulonglong2*>(dst + jt * 8);
        d[0] = make_ulonglong2(A.v[0], A.v[1]);
        d[1] = make_ulonglong2(A.v[2], A.v[3]);
        d[2] = make_ulonglong2(A.v[4], A.v[5]);
        d[3] = make_ulonglong2(A.v[6], A.v[7]);
    }
}

// ---------------------------------------------------------------- prep ------
__global__ __launch_bounds__(256) void prep_kernel(
    const float* __restrict__ We, const float* __restrict__ be,
    const float* __restrict__ Wm1, const float* __restrict__ bm1) {
    __shared__ float sWe[2048];   // 32 x 64
    __shared__ float sA3[4096];   // 64 x 64 (Wm1 rows 128..191)
    int t = threadIdx.x;

    for (int i = t; i < 512; i += 256)
        reinterpret_cast<float4*>(sWe)[i] =
            reinterpret_cast<const float4*>(We)[i];
    for (int i = t; i < 1024; i += 256)
        reinterpret_cast<float4*>(sA3)[i] =
            reinterpret_cast<const float4*>(Wm1 + 128 * 64)[i];
    __syncthreads();

    // Rows 0..31 of Wz: C = We @ A3   (2048 outputs, 8 per thread)
#pragma unroll
    for (int u = 0; u < 8; ++u) {
        int idx = u * 256 + t;
        int i = idx >> 6, j = idx & 63;
        float s = 0.f;
#pragma unroll 8
        for (int k = 0; k < 64; ++k)
            s = fmaf(sWe[i * 64 + k], sA3[k * 64 + j], s);
        g_Wz[idx] = s;
    }
    // Rows 32..63 of Wz: D = Wm1 rows 192..223 (contiguous copy)
    for (int i = t; i < 2048; i += 256)
        g_Wz[2048 + i] = Wm1[192 * 64 + i];
    // bc = bm1 + be @ A3
    if (t < 64) {
        float s = bm1[t];
#pragma unroll 8
        for (int k = 0; k < 64; ++k)
            s = fmaf(be[k], sA3[k * 64 + t], s);
        g_bc[t] = s;
    }
}

// ------------------------------------------------------------ node stage ----
// smem: W1(4096) W2(4096) A1(4096) A2(4096) b1(64) b2(64) x(128*65)
#define NODE_SMEM_FLOATS (16512 + 128 * 65)
#define NODE_SMEM_BYTES (NODE_SMEM_FLOATS * 4)

__global__ __launch_bounds__(128) void node_kernel(
    const float* __restrict__ x, const float* __restrict__ W1,
    const float* __restrict__ b1, const float* __restrict__ W2,
    const float* __restrict__ b2, const float* __restrict__ Wm1, int N) {
    extern __shared__ float sm[];
    float* sW1 = sm;
    float* sW2 = sm + 4096;
    float* sA1 = sm + 8192;
    float* sA2 = sm + 12288;
    float* sb1 = sm + 16384;
    float* sb2 = sm + 16448;
    float* sx  = sm + 16512;  // 128 rows, stride 65 (bank-conflict-free)
    int t = threadIdx.x;

    for (int i = t; i < 1024; i += 128) {
        reinterpret_cast<float4*>(sW1)[i] = reinterpret_cast<const float4*>(W1)[i];
        reinterpret_cast<float4*>(sW2)[i] = reinterpret_cast<const float4*>(W2)[i];
        reinterpret_cast<float4*>(sA1)[i] = reinterpret_cast<const float4*>(Wm1)[i];
        reinterpret_cast<float4*>(sA2)[i] = reinterpret_cast<const float4*>(Wm1)[1024 + i];
    }
    if (t < 64) { sb1[t] = b1[t]; sb2[t] = b2[t]; }

    int n0 = blockIdx.x * 128;
    for (int i = t; i < 128 * 16; i += 128) {
        int r = i >> 4, c = i & 15;
        if (n0 + r < N) {
            float4 v = __ldcs(reinterpret_cast<const float4*>(x) +
                              (size_t)(n0 + r) * 16 + c);
            float* d = sx + r * 65 + c * 4;
            d[0] = v.x; d[1] = v.y; d[2] = v.z; d[3] = v.w;
        }
    }
    __syncthreads();

    int n = n0 + t;
    if (n >= N) return;

    float* zrow = sx + t * 65;  // this thread's private row
    float h[64];

    layer_relu2(zrow, sW1, sb1, h);        // h1
#pragma unroll
    for (int j = 0; j < 64; ++j) zrow[j] = h[j];
    layer_relu2(zrow, sW2, sb2, h);        // h2 = h_nodes[n]
#pragma unroll
    for (int j = 0; j < 64; ++j) zrow[j] = h[j];

    proj_store2(zrow, sA1, reinterpret_cast<u64*>(g_p + (size_t)n * 64));
    proj_store2(zrow, sA2, reinterpret_cast<u64*>(g_q + (size_t)n * 64));
}

// ------------------------------------------------------------ edge stage ----
// smem: Wz(4096) bc(64) Wm2(64) z(128*65)
#define EDGE_SMEM_FLOATS (4224 + 128 * 65)
#define EDGE_SMEM_BYTES (EDGE_SMEM_FLOATS * 4)

__global__ __launch_bounds__(128) void edge_kernel(
    const float* __restrict__ ea, const float* __restrict__ te,
    const int* __restrict__ src, const int* __restrict__ dst,
    const float* __restrict__ Wm2, const float* __restrict__ bm2,
    float* __restrict__ out, int E) {
    extern __shared__ float sm[];
    float* sWz  = sm;
    float* sbc  = sm + 4096;
    float* sW2v = sm + 4160;
    float* zs   = sm + 4224;  // 128 rows, stride 65
    int t = threadIdx.x;

    for (int i = t; i < 1024; i += 128)
        reinterpret_cast<float4*>(sWz)[i] = reinterpret_cast<const float4*>(g_Wz)[i];
    if (t < 64) { sbc[t] = g_bc[t]; sW2v[t] = Wm2[t]; }

    int e0 = blockIdx.x * 128;
    for (int i = t; i < 128 * 8; i += 128) {
        int r = i >> 3, c = i & 7;
        if (e0 + r < E) {
            float4 v = __ldcs(reinterpret_cast<const float4*>(ea) +
                              (size_t)(e0 + r) * 8 + c);
            float* d = zs + r * 65 + c * 4;
            d[0] = v.x; d[1] = v.y; d[2] = v.z; d[3] = v.w;
            float4 u = __ldcs(reinterpret_cast<const float4*>(te) +
                              (size_t)(e0 + r) * 8 + c);
            float* d2 = zs + r * 65 + 32 + c * 4;
            d2[0] = u.x; d2[1] = u.y; d2[2] = u.z; d2[3] = u.w;
        }
    }
    __syncthreads();

    int e = e0 + t;
    if (e >= E) return;

    const float* zr = zs + t * 65;
    const float* pg = g_p + (size_t)src[e] * 64;
    const float* qg = g_q + (size_t)dst[e] * 64;
    float acc = bm2[0];

#pragma unroll
    for (int jt = 0; jt < 4; ++jt) {
        const u64* bb = reinterpret_cast<const u64*>(sbc) + jt * 8;
        AccP A;
#pragma unroll
        for (int i = 0; i < 8; ++i) A.v[i] = bb[i];
        tile_gemm2(zr, sWz, jt, A);

        float hvals[16];
#pragma unroll
        for (int i = 0; i < 8; ++i) {
            float2 f = unpack2(A.v[i]);
            hvals[2 * i] = f.x; hvals[2 * i + 1] = f.y;
        }
        float pv[16], qv[16];
#pragma unroll
        for (int c = 0; c < 4; ++c) {
            float4 p4 = reinterpret_cast<const float4*>(pg + jt * 16)[c];
            float4 q4 = reinterpret_cast<const float4*>(qg + jt * 16)[c];
            pv[4 * c] = p4.x; pv[4 * c + 1] = p4.y;
            pv[4 * c + 2] = p4.z; pv[4 * c + 3] = p4.w;
            qv[4 * c] = q4.x; qv[4 * c + 1] = q4.y;
            qv[4 * c + 2] = q4.z; qv[4 * c + 3] = q4.w;
        }
#pragma unroll
        for (int o = 0; o < 16; ++o) {
            float r = fmaxf(hvals[o] + pv[o] + qv[o], 0.f);
            acc = fmaf(r, sW2v[jt * 16 + o], acc);
        }
    }
    out[e] = acc;
}

// ------------------------------------------------------------ launch --------
extern "C" void kernel_launch(void* const* d_in, const int* in_sizes, int n_in,
                              void* d_out, int out_size) {
    const float* x   = (const float*)d_in[0];
    const int*   src = (const int*)d_in[1];
    const int*   dst = (const int*)d_in[2];
    const float* ea  = (const float*)d_in[3];
    const float* te  = (const float*)d_in[4];
    const float* W1  = (const float*)d_in[5];
    const float* b1  = (const float*)d_in[6];
    const float* W2  = (const float*)d_in[7];
    const float* b2  = (const float*)d_in[8];
    const float* We  = (const float*)d_in[9];
    const float* be  = (const float*)d_in[10];
    const float* Wm1 = (const float*)d_in[11];
    const float* bm1 = (const float*)d_in[12];
    const float* Wm2 = (const float*)d_in[13];
    const float* bm2 = (const float*)d_in[14];
    float* out = (float*)d_out;

    int N = in_sizes[0] / 64;
    int E = in_sizes[1];

    // One-time host-side setup; kept off the graph-capture call path.
    static bool attrs_set = false;
    if (!attrs_set) {
        cudaFuncSetAttribute(node_kernel,
                             cudaFuncAttributeMaxDynamicSharedMemorySize,
                             NODE_SMEM_BYTES);
        cudaFuncSetAttribute(edge_kernel,
                             cudaFuncAttributeMaxDynamicSharedMemorySize,
                             EDGE_SMEM_BYTES);
        attrs_set = true;
    }

    prep_kernel<<<1, 256>>>(We, be, Wm1, bm1);
    node_kernel<<<(N + 127) / 128, 128, NODE_SMEM_BYTES>>>(x, W1, b1, W2, b2,
                                                           Wm1, N);
    edge_kernel<<<(E + 127) / 128, 128, EDGE_SMEM_BYTES>>>(ea, te, src, dst,
                                                           Wm2, bm2, out, E);
}

// round 6
// speedup vs baseline: 1.6121x; 1.6121x over previous
#include <cuda_runtime.h>
#include <cstdint>

// ----------------------------------------------------------------------------
// TGAT edge classifier.
//   node:  p[n] = h_nodes[n] @ Wm1[0:64], q[n] = h_nodes[n] @ Wm1[64:128] (FFMA)
//   prep:  Wz = [We @ Wm1[128:192] ; Wm1[192:224]] (64x64), bc, and pre-packed
//          per-lane bf16 B fragments (hi/lo split) for mma.sync.
//   edge:  hidden = z @ Wz via mma.sync m16n8k16 bf16 (3-term split),
//          + cooperative-gathered (p[src]+q[dst]+bc), relu, dot Wm2.
// ----------------------------------------------------------------------------

#define N_CAP 100000
#define H 64

typedef unsigned long long u64;
typedef uint32_t u32;

__device__ float g_p[N_CAP * H];
__device__ float g_q[N_CAP * H];
__device__ float g_Wz[H * H];     // [k][n] fp32
__device__ float g_bc[H];
__device__ u32 g_Bfh[2048];       // B fragments hi: [tile=kt*8+nt][lane][2] u32
__device__ u32 g_Bfl[2048];       // B fragments lo

// ---------------------------------------------------------- PTX helpers -----
__device__ __forceinline__ u32 smem_u32(const void* p) {
    u32 a;
    asm("{ .reg .u64 t; cvta.to.shared.u64 t, %1; cvt.u32.u64 %0, t; }"
        : "=r"(a) : "l"(p));
    return a;
}
// bf16x2 = {hi half = bf16(h), lo half = bf16(l)}
__device__ __forceinline__ u32 bf2(float h, float l) {
    u32 r;
    asm("cvt.rn.bf16x2.f32 %0, %1, %2;" : "=r"(r) : "f"(h), "f"(l));
    return r;
}
__device__ __forceinline__ void ldmatrix_x4(u32* r, u32 addr) {
    asm volatile(
        "ldmatrix.sync.aligned.m8n8.x4.shared.b16 {%0,%1,%2,%3}, [%4];"
        : "=r"(r[0]), "=r"(r[1]), "=r"(r[2]), "=r"(r[3]) : "r"(addr));
}
__device__ __forceinline__ void mma_bf16(float* c, const u32* a, const u32* b) {
    asm volatile(
        "mma.sync.aligned.m16n8k16.row.col.f32.bf16.bf16.f32 "
        "{%0,%1,%2,%3}, {%4,%5,%6,%7}, {%8,%9}, {%0,%1,%2,%3};"
        : "+f"(c[0]), "+f"(c[1]), "+f"(c[2]), "+f"(c[3])
        : "r"(a[0]), "r"(a[1]), "r"(a[2]), "r"(a[3]), "r"(b[0]), "r"(b[1]));
}

// ---------------------------------------------------- packed f32x2 (node) ---
__device__ __forceinline__ u64 pack2(float a) {
    u64 r; asm("mov.b64 %0, {%1, %1};" : "=l"(r) : "f"(a)); return r;
}
__device__ __forceinline__ void fma2(u64& d, u64 a, u64 b) {
    asm("fma.rn.f32x2 %0, %1, %2, %0;" : "+l"(d) : "l"(a), "l"(b));
}
__device__ __forceinline__ float2 unpack2(u64 v) {
    float2 f; asm("mov.b64 {%0, %1}, %2;" : "=f"(f.x), "=f"(f.y) : "l"(v)); return f;
}

struct AccP { u64 v[8]; };

__device__ __forceinline__ void tile_gemm2(const float* __restrict__ zrow,
                                           const float* __restrict__ wbase,
                                           int jt, AccP& A) {
#pragma unroll 8
    for (int k = 0; k < 64; ++k) {
        u64 zz = pack2(zrow[k]);
        const ulonglong2* w =
            reinterpret_cast<const ulonglong2*>(wbase + k * 64 + jt * 16);
        ulonglong2 w0 = w[0], w1 = w[1], w2 = w[2], w3 = w[3];
        fma2(A.v[0], zz, w0.x); fma2(A.v[1], zz, w0.y);
        fma2(A.v[2], zz, w1.x); fma2(A.v[3], zz, w1.y);
        fma2(A.v[4], zz, w2.x); fma2(A.v[5], zz, w2.y);
        fma2(A.v[6], zz, w3.x); fma2(A.v[7], zz, w3.y);
    }
}

__device__ __forceinline__ void layer_relu2(const float* __restrict__ zrow,
                                            const float* __restrict__ W,
                                            const float* __restrict__ b,
                                            float* __restrict__ hout) {
#pragma unroll
    for (int jt = 0; jt < 4; ++jt) {
        const u64* bb = reinterpret_cast<const u64*>(b) + jt * 8;
        AccP A;
#pragma unroll
        for (int i = 0; i < 8; ++i) A.v[i] = bb[i];
        tile_gemm2(zrow, W, jt, A);
        float* o = hout + jt * 16;
#pragma unroll
        for (int i = 0; i < 8; ++i) {
            float2 f = unpack2(A.v[i]);
            o[2 * i]     = fmaxf(f.x, 0.f);
            o[2 * i + 1] = fmaxf(f.y, 0.f);
        }
    }
}

__device__ __forceinline__ void proj_store2(const float* __restrict__ zrow,
                                            const float* __restrict__ W,
                                            u64* __restrict__ dst) {
#pragma unroll
    for (int jt = 0; jt < 4; ++jt) {
        AccP A;
#pragma unroll
        for (int i = 0; i < 8; ++i) A.v[i] = 0ull;
        tile_gemm2(zrow, W, jt, A);
        ulonglong2* d = reinterpret_cast<ulonglong2*>(dst + jt * 8);
        d[0] = make_ulonglong2(A.v[0], A.v[1]);
        d[1] = make_ulonglong2(A.v[2], A.v[3]);
        d[2] = make_ulonglong2(A.v[4], A.v[5]);
        d[3] = make_ulonglong2(A.v[6], A.v[7]);
    }
}

// ---------------------------------------------------------------- prep ------
__global__ __launch_bounds__(256) void prep_kernel(
    const float* __restrict__ We, const float* __restrict__ be,
    const float* __restrict__ Wm1, const float* __restrict__ bm1) {
    __shared__ float sWe[2048];
    __shared__ float sA3[4096];
    int t = threadIdx.x;

    for (int i = t; i < 512; i += 256)
        reinterpret_cast<float4*>(sWe)[i] = reinterpret_cast<const float4*>(We)[i];
    for (int i = t; i < 1024; i += 256)
        reinterpret_cast<float4*>(sA3)[i] =
            reinterpret_cast<const float4*>(Wm1 + 128 * 64)[i];
    __syncthreads();

    // Wz rows 0..31: C = We @ A3
#pragma unroll
    for (int u = 0; u < 8; ++u) {
        int idx = u * 256 + t;
        int i = idx >> 6, j = idx & 63;
        float s = 0.f;
#pragma unroll 8
        for (int k = 0; k < 64; ++k)
            s = fmaf(sWe[i * 64 + k], sA3[k * 64 + j], s);
        g_Wz[idx] = s;
    }
    // Wz rows 32..63: copy Wm1 rows 192..223
    for (int i = t; i < 2048; i += 256)
        g_Wz[2048 + i] = Wm1[192 * 64 + i];
    // bc = bm1 + be @ A3
    if (t < 64) {
        float s = bm1[t];
#pragma unroll 8
        for (int k = 0; k < 64; ++k)
            s = fmaf(be[k], sA3[k * 64 + t], s);
        g_bc[t] = s;
    }
    __syncthreads();

    // Pre-packed per-lane B fragments for mma.sync m16n8k16 (B col-major k x n):
    // b_reg holds {B[k0][n] (lo half), B[k0+1][n] (hi half)},
    // k0 = kt*16 + 2*tg + reg*8, n = nt*8 + g,  g=lane>>2, tg=lane&3.
    for (int idx = t; idx < 2048; idx += 256) {
        int reg  = idx & 1;
        int lane = (idx >> 1) & 31;
        int tile = idx >> 6;           // kt*8 + nt
        int kt = tile >> 3, nt = tile & 7;
        int g = lane >> 2, tg = lane & 3;
        int n = nt * 8 + g;
        int k0 = kt * 16 + 2 * tg + reg * 8;
        float v0 = g_Wz[k0 * 64 + n];
        float v1 = g_Wz[(k0 + 1) * 64 + n];
        u32 ph = bf2(v1, v0);
        float h0 = __uint_as_float(ph << 16);
        float h1 = __uint_as_float(ph & 0xFFFF0000u);
        u32 pl = bf2(v1 - h1, v0 - h0);
        g_Bfh[idx] = ph;
        g_Bfl[idx] = pl;
    }
}

// ------------------------------------------------------------ node stage ----
// smem: W1(4096) W2(4096) A1(4096) A2(4096) b1(64) b2(64) x(128*65)
#define NODE_SMEM_FLOATS (16512 + 128 * 65)
#define NODE_SMEM_BYTES (NODE_SMEM_FLOATS * 4)

__global__ __launch_bounds__(128) void node_kernel(
    const float* __restrict__ x, const float* __restrict__ W1,
    const float* __restrict__ b1, const float* __restrict__ W2,
    const float* __restrict__ b2, const float* __restrict__ Wm1, int N) {
    extern __shared__ float sm[];
    float* sW1 = sm;
    float* sW2 = sm + 4096;
    float* sA1 = sm + 8192;
    float* sA2 = sm + 12288;
    float* sb1 = sm + 16384;
    float* sb2 = sm + 16448;
    float* sx  = sm + 16512;  // 128 rows, stride 65
    int t = threadIdx.x;

    for (int i = t; i < 1024; i += 128) {
        reinterpret_cast<float4*>(sW1)[i] = reinterpret_cast<const float4*>(W1)[i];
        reinterpret_cast<float4*>(sW2)[i] = reinterpret_cast<const float4*>(W2)[i];
        reinterpret_cast<float4*>(sA1)[i] = reinterpret_cast<const float4*>(Wm1)[i];
        reinterpret_cast<float4*>(sA2)[i] = reinterpret_cast<const float4*>(Wm1)[1024 + i];
    }
    if (t < 64) { sb1[t] = b1[t]; sb2[t] = b2[t]; }

    int n0 = blockIdx.x * 128;
    for (int i = t; i < 128 * 16; i += 128) {
        int r = i >> 4, c = i & 15;
        if (n0 + r < N) {
            float4 v = __ldcs(reinterpret_cast<const float4*>(x) +
                              (size_t)(n0 + r) * 16 + c);
            float* d = sx + r * 65 + c * 4;
            d[0] = v.x; d[1] = v.y; d[2] = v.z; d[3] = v.w;
        }
    }
    __syncthreads();

    int n = n0 + t;
    if (n >= N) return;

    float* zrow = sx + t * 65;
    float h[64];

    layer_relu2(zrow, sW1, sb1, h);
#pragma unroll
    for (int j = 0; j < 64; ++j) zrow[j] = h[j];
    layer_relu2(zrow, sW2, sb2, h);
#pragma unroll
    for (int j = 0; j < 64; ++j) zrow[j] = h[j];

    proj_store2(zrow, sA1, reinterpret_cast<u64*>(g_p + (size_t)n * 64));
    proj_store2(zrow, sA2, reinterpret_cast<u64*>(g_q + (size_t)n * 64));
}

// ------------------------------------------------------------ edge stage ----
// smem bytes: BFH 0 (8K), BFL 8192 (8K), WM2 16384 (256), BC 16640 (256),
//   SRC 16896 (512), DST 17408 (512), U 17920 (36864: zh[128][72]bf16 +
//   zl[128][72]bf16, later reused as pq[128][68]f32)  -> total 54784
#define EB_BFH  0
#define EB_BFL  8192
#define EB_WM2  16384
#define EB_BC   16640
#define EB_SRC  16896
#define EB_DST  17408
#define EB_U    17920
#define EB_ZL   (EB_U + 18432)
#define EDGE_SMEM_BYTES 54784

__global__ __launch_bounds__(128, 4) void edge_kernel(
    const float* __restrict__ ea, const float* __restrict__ te,
    const int* __restrict__ src, const int* __restrict__ dst,
    const float* __restrict__ Wm2, const float* __restrict__ bm2,
    float* __restrict__ out, int E) {
    extern __shared__ char smc[];
    float* smf = reinterpret_cast<float*>(smc);
    int t = threadIdx.x;
    int lane = t & 31, wid = t >> 5;
    int wbase = wid * 32;
    u32 sb = smem_u32(smc);

    // stage B fragments, wm2, bc, indices
    for (int i = t; i < 512; i += 128) {
        reinterpret_cast<uint4*>(smc + EB_BFH)[i] =
            reinterpret_cast<const uint4*>(g_Bfh)[i];
        reinterpret_cast<uint4*>(smc + EB_BFL)[i] =
            reinterpret_cast<const uint4*>(g_Bfl)[i];
    }
    if (t < 64) {
        smf[EB_WM2 / 4 + t] = Wm2[t];
        smf[EB_BC / 4 + t]  = g_bc[t];
    }
    int e0 = blockIdx.x * 128;
    int e = e0 + t;
    bool valid = e < E;
    reinterpret_cast<int*>(smc + EB_SRC)[t] = valid ? src[e] : 0;
    reinterpret_cast<int*>(smc + EB_DST)[t] = valid ? dst[e] : 0;

    // stage z row (bf16 hi/lo split), rows stride 144B (72 bf16)
    {
        float z[64];
        if (valid) {
            const float4* er = reinterpret_cast<const float4*>(ea) + (size_t)e * 8;
            const float4* tr = reinterpret_cast<const float4*>(te) + (size_t)e * 8;
#pragma unroll
            for (int i = 0; i < 8; ++i) {
                float4 v = er[i];
                z[4 * i] = v.x; z[4 * i + 1] = v.y;
                z[4 * i + 2] = v.z; z[4 * i + 3] = v.w;
                float4 u = tr[i];
                z[32 + 4 * i] = u.x; z[33 + 4 * i] = u.y;
                z[34 + 4 * i] = u.z; z[35 + 4 * i] = u.w;
            }
        } else {
#pragma unroll
            for (int i = 0; i < 64; ++i) z[i] = 0.f;
        }
        u32* zh = reinterpret_cast<u32*>(smc + EB_U + t * 144);
        u32* zl = reinterpret_cast<u32*>(smc + EB_ZL + t * 144);
#pragma unroll
        for (int c = 0; c < 32; ++c) {
            float v0 = z[2 * c], v1 = z[2 * c + 1];
            u32 ph = bf2(v1, v0);
            float h0 = __uint_as_float(ph << 16);
            float h1 = __uint_as_float(ph & 0xFFFF0000u);
            zh[c] = ph;
            zl[c] = bf2(v1 - h1, v0 - h0);
        }
    }
    __syncthreads();

    // MMA phase: acc[mt][nt][4] over 3 split terms
    float acc[2][8][4];
#pragma unroll
    for (int mt = 0; mt < 2; ++mt)
#pragma unroll
        for (int nt = 0; nt < 8; ++nt)
#pragma unroll
            for (int i = 0; i < 4; ++i) acc[mt][nt][i] = 0.f;

    {
        // ldmatrix lane address pattern for 16x16 A tiles
        int lrow_off = ((lane >> 3) & 1) * 8 + (lane & 7);
        int lcol = ((lane >> 4) << 3);  // 0 or 8 (bf16 units)
#pragma unroll
        for (int kt = 0; kt < 4; ++kt) {
            u32 Ah[2][4], Al[2][4];
#pragma unroll
            for (int mt = 0; mt < 2; ++mt) {
                int row = wbase + mt * 16 + lrow_off;
                u32 byteoff = (u32)(row * 144 + (kt * 16 + lcol) * 2);
                ldmatrix_x4(Ah[mt], sb + EB_U + byteoff);
                ldmatrix_x4(Al[mt], sb + EB_ZL + byteoff);
            }
#pragma unroll
            for (int nt = 0; nt < 8; ++nt) {
                int tile = kt * 8 + nt;
                uint2 bh = *reinterpret_cast<const uint2*>(
                    smc + EB_BFH + (tile * 32 + lane) * 8);
                uint2 bl = *reinterpret_cast<const uint2*>(
                    smc + EB_BFL + (tile * 32 + lane) * 8);
                u32 bhv[2] = {bh.x, bh.y};
                u32 blv[2] = {bl.x, bl.y};
#pragma unroll
                for (int mt = 0; mt < 2; ++mt) {
                    mma_bf16(acc[mt][nt], Ah[mt], bhv);
                    mma_bf16(acc[mt][nt], Ah[mt], blv);
                    mma_bf16(acc[mt][nt], Al[mt], bhv);
                }
            }
        }
    }
    __syncthreads();  // all warps done reading zh/zl; U region reused as pq

    // cooperative gather: pq[r] = p[src[r]] + q[dst[r]] + bc  (128B granular)
    {
        const int* ss = reinterpret_cast<const int*>(smc + EB_SRC);
        const int* dd = reinterpret_cast<const int*>(smc + EB_DST);
        const float4* bc4 = reinterpret_cast<const float4*>(smc + EB_BC);
        float* pqs = smf + EB_U / 4;
#pragma unroll
        for (int it = 0; it < 16; ++it) {
            int id = it * 128 + t;
            int r = id >> 4, s = id & 15;
            float4 pv = __ldg(reinterpret_cast<const float4*>(
                                  g_p + (size_t)ss[r] * 64) + s);
            float4 qv = __ldg(reinterpret_cast<const float4*>(
                                  g_q + (size_t)dd[r] * 64) + s);
            float4 bcv = bc4[s];
            float4 o;
            o.x = pv.x + qv.x + bcv.x; o.y = pv.y + qv.y + bcv.y;
            o.z = pv.z + qv.z + bcv.z; o.w = pv.w + qv.w + bcv.w;
            reinterpret_cast<float4*>(pqs + r * 68)[s] = o;
        }
    }
    __syncthreads();

    // epilogue: out[row] = relu(acc + pq) . wm2 + bm2, quad-reduced
    {
        const float* pqs = smf + EB_U / 4;
        const float* wms = smf + EB_WM2 / 4;
        int g = lane >> 2, tg = lane & 3;
        float bm2v = __ldg(bm2);
#pragma unroll
        for (int mt = 0; mt < 2; ++mt) {
            int r0 = wbase + mt * 16 + g;
            int r1 = r0 + 8;
            float sum0 = 0.f, sum1 = 0.f;
#pragma unroll
            for (int nt = 0; nt < 8; ++nt) {
                int c0 = nt * 8 + 2 * tg;
                float2 w  = *reinterpret_cast<const float2*>(wms + c0);
                float2 p0 = *reinterpret_cast<const float2*>(pqs + r0 * 68 + c0);
                float2 p1 = *reinterpret_cast<const float2*>(pqs + r1 * 68 + c0);
                sum0 = fmaf(fmaxf(acc[mt][nt][0] + p0.x, 0.f), w.x, sum0);
                sum0 = fmaf(fmaxf(acc[mt][nt][1] + p0.y, 0.f), w.y, sum0);
                sum1 = fmaf(fmaxf(acc[mt][nt][2] + p1.x, 0.f), w.x, sum1);
                sum1 = fmaf(fmaxf(acc[mt][nt][3] + p1.y, 0.f), w.y, sum1);
            }
            sum0 += __shfl_xor_sync(0xFFFFFFFFu, sum0, 1);
            sum0 += __shfl_xor_sync(0xFFFFFFFFu, sum0, 2);
            sum1 += __shfl_xor_sync(0xFFFFFFFFu, sum1, 1);
            sum1 += __shfl_xor_sync(0xFFFFFFFFu, sum1, 2);
            if (tg == 0) {
                if (e0 + r0 < E) out[e0 + r0] = sum0 + bm2v;
                if (e0 + r1 < E) out[e0 + r1] = sum1 + bm2v;
            }
        }
    }
}

// ------------------------------------------------------------ launch --------
extern "C" void kernel_launch(void* const* d_in, const int* in_sizes, int n_in,
                              void* d_out, int out_size) {
    const float* x   = (const float*)d_in[0];
    const int*   src = (const int*)d_in[1];
    const int*   dst = (const int*)d_in[2];
    const float* ea  = (const float*)d_in[3];
    const float* te  = (const float*)d_in[4];
    const float* W1  = (const float*)d_in[5];
    const float* b1  = (const float*)d_in[6];
    const float* W2  = (const float*)d_in[7];
    const float* b2  = (const float*)d_in[8];
    const float* We  = (const float*)d_in[9];
    const float* be  = (const float*)d_in[10];
    const float* Wm1 = (const float*)d_in[11];
    const float* bm1 = (const float*)d_in[12];
    const float* Wm2 = (const float*)d_in[13];
    const float* bm2 = (const float*)d_in[14];
    float* out = (float*)d_out;

    int N = in_sizes[0] / 64;
    int E = in_sizes[1];

    static bool attrs_set = false;
    if (!attrs_set) {
        cudaFuncSetAttribute(node_kernel,
                             cudaFuncAttributeMaxDynamicSharedMemorySize,
                             NODE_SMEM_BYTES);
        cudaFuncSetAttribute(edge_kernel,
                             cudaFuncAttributeMaxDynamicSharedMemorySize,
                             EDGE_SMEM_BYTES);
        attrs_set = true;
    }

    prep_kernel<<<1, 256>>>(We, be, Wm1, bm1);
    node_kernel<<<(N + 127) / 128, 128, NODE_SMEM_BYTES>>>(x, W1, b1, W2, b2,
                                                           Wm1, N);
    edge_kernel<<<(E + 127) / 128, 128, EDGE_SMEM_BYTES>>>(ea, te, src, dst,
                                                           Wm2, bm2, out, E);
}

// round 8
// speedup vs baseline: 2.3245x; 1.4419x over previous
#include <cuda_runtime.h>
#include <cstdint>

// ----------------------------------------------------------------------------
// TGAT edge classifier.
//   prep (2 blocks): Wz = [We @ Wm1[128:192] ; Wm1[192:224]], bc, and
//     pre-packed per-lane bf16 mma.sync B fragments (hi/lo split) for
//     Wz, W1, W2, A1 (=Wm1[0:64]), A2 (=Wm1[64:128]).
//   node: 4 chained 64x64 GEMMs per 128-row block via mma.sync bf16x2-split,
//     fully warp-local (no block barriers): h1=relu(x@W1+b1),
//     h2=relu(h1@W2+b2), p=h2@A1, q=h2@A2.
//   edge: hidden = z @ Wz via mma.sync (3-term split), + cooperative-gathered
//     (p[src]+q[dst]+bc), relu, dot Wm2.
// ----------------------------------------------------------------------------

#define N_CAP 100000
#define H 64

typedef unsigned long long u64;
typedef uint32_t u32;

__device__ float g_p[N_CAP * H];
__device__ float g_q[N_CAP * H];
__device__ float g_Wz[H * H];     // [k][n] fp32
__device__ float g_bc[H];
__device__ __align__(16) u32 g_Bfh[2048];      // edge Wz fragments hi
__device__ __align__(16) u32 g_Bfl[2048];      // edge Wz fragments lo
__device__ __align__(16) u32 g_Fh[4][2048];    // node W1,W2,A1,A2 frags hi
__device__ __align__(16) u32 g_Fl[4][2048];    // node frags lo

// ---------------------------------------------------------- PTX helpers -----
__device__ __forceinline__ u32 smem_u32(const void* p) {
    u32 a;
    asm("{ .reg .u64 t; cvta.to.shared.u64 t, %1; cvt.u32.u64 %0, t; }"
        : "=r"(a) : "l"(p));
    return a;
}
// bf16x2 = {hi half = bf16(h), lo half = bf16(l)}
__device__ __forceinline__ u32 bf2(float h, float l) {
    u32 r;
    asm("cvt.rn.bf16x2.f32 %0, %1, %2;" : "=r"(r) : "f"(h), "f"(l));
    return r;
}
__device__ __forceinline__ void ldmatrix_x4(u32* r, u32 addr) {
    asm volatile(
        "ldmatrix.sync.aligned.m8n8.x4.shared.b16 {%0,%1,%2,%3}, [%4];"
        : "=r"(r[0]), "=r"(r[1]), "=r"(r[2]), "=r"(r[3]) : "r"(addr));
}
__device__ __forceinline__ void mma_bf16(float* c, const u32* a, const u32* b) {
    asm volatile(
        "mma.sync.aligned.m16n8k16.row.col.f32.bf16.bf16.f32 "
        "{%0,%1,%2,%3}, {%4,%5,%6,%7}, {%8,%9}, {%0,%1,%2,%3};"
        : "+f"(c[0]), "+f"(c[1]), "+f"(c[2]), "+f"(c[3])
        : "r"(a[0]), "r"(a[1]), "r"(a[2]), "r"(a[3]), "r"(b[0]), "r"(b[1]));
}

// split a float pair into bf16 hi and lo packed words
__device__ __forceinline__ void split_pair(float v0, float v1, u32& ph, u32& pl) {
    ph = bf2(v1, v0);
    float h0 = __uint_as_float(ph << 16);
    float h1 = __uint_as_float(ph & 0xFFFF0000u);
    pl = bf2(v1 - h1, v0 - h0);
}

// ---------------------------------------------------------------- prep ------
// grid = 2 blocks x 256 threads.
// block 0: Wz, bc, edge fragments.  block 1: node weight fragments.
__global__ __launch_bounds__(256) void prep_kernel(
    const float* __restrict__ We, const float* __restrict__ be,
    const float* __restrict__ Wm1, const float* __restrict__ bm1,
    const float* __restrict__ W1, const float* __restrict__ W2) {
    int t = threadIdx.x;

    if (blockIdx.x == 1) {
        // node weight fragments: matrices [k][n] row-major, 64x64 each
        const float* mats[4] = {W1, W2, Wm1, Wm1 + 64 * 64};
#pragma unroll
        for (int m = 0; m < 4; ++m) {
            const float* M = mats[m];
            for (int idx = t; idx < 2048; idx += 256) {
                int reg  = idx & 1;
                int lane = (idx >> 1) & 31;
                int tile = idx >> 6;           // kt*8 + nt
                int kt = tile >> 3, nt = tile & 7;
                int g = lane >> 2, tg = lane & 3;
                int n = nt * 8 + g;
                int k0 = kt * 16 + 2 * tg + reg * 8;
                u32 ph, pl;
                split_pair(M[k0 * 64 + n], M[(k0 + 1) * 64 + n], ph, pl);
                g_Fh[m][idx] = ph;
                g_Fl[m][idx] = pl;
            }
        }
        return;
    }

    __shared__ float sWe[2048];
    __shared__ float sA3[4096];

    for (int i = t; i < 512; i += 256)
        reinterpret_cast<float4*>(sWe)[i] = reinterpret_cast<const float4*>(We)[i];
    for (int i = t; i < 1024; i += 256)
        reinterpret_cast<float4*>(sA3)[i] =
            reinterpret_cast<const float4*>(Wm1 + 128 * 64)[i];
    __syncthreads();

    // Wz rows 0..31: C = We @ A3
#pragma unroll
    for (int u = 0; u < 8; ++u) {
        int idx = u * 256 + t;
        int i = idx >> 6, j = idx & 63;
        float s = 0.f;
#pragma unroll 8
        for (int k = 0; k < 64; ++k)
            s = fmaf(sWe[i * 64 + k], sA3[k * 64 + j], s);
        g_Wz[idx] = s;
    }
    // Wz rows 32..63: copy Wm1 rows 192..223
    for (int i = t; i < 2048; i += 256)
        g_Wz[2048 + i] = Wm1[192 * 64 + i];
    // bc = bm1 + be @ A3
    if (t < 64) {
        float s = bm1[t];
#pragma unroll 8
        for (int k = 0; k < 64; ++k)
            s = fmaf(be[k], sA3[k * 64 + t], s);
        g_bc[t] = s;
    }
    __syncthreads();

    // edge Wz fragments
    for (int idx = t; idx < 2048; idx += 256) {
        int reg  = idx & 1;
        int lane = (idx >> 1) & 31;
        int tile = idx >> 6;
        int kt = tile >> 3, nt = tile & 7;
        int g = lane >> 2, tg = lane & 3;
        int n = nt * 8 + g;
        int k0 = kt * 16 + 2 * tg + reg * 8;
        u32 ph, pl;
        split_pair(g_Wz[k0 * 64 + n], g_Wz[(k0 + 1) * 64 + n], ph, pl);
        g_Bfh[idx] = ph;
        g_Bfl[idx] = pl;
    }
}

// ------------------------------------------------------------ node stage ----
// smem: zh [128 rows x 144B] bf16-hi, zl same (lo). 36864 bytes. Warp-local.
#define NB_ZH 0
#define NB_ZL 18432
#define NODE_SMEM_BYTES 36864

// one GEMM stage with bias+relu, in-place bf16 split write-back (warp-local)
__device__ __forceinline__ void node_stage_relu(
    char* smc, u32 sb, const u32* Bh, const u32* Bl,
    const float* __restrict__ bias, int wbase, int lane) {
    float acc[2][8][4];
#pragma unroll
    for (int mt = 0; mt < 2; ++mt)
#pragma unroll
        for (int nt = 0; nt < 8; ++nt)
#pragma unroll
            for (int i = 0; i < 4; ++i) acc[mt][nt][i] = 0.f;

    int lrow_off = ((lane >> 3) & 1) * 8 + (lane & 7);
    int lcol = ((lane >> 4) << 3);
#pragma unroll
    for (int kt = 0; kt < 4; ++kt) {
        u32 Ah[2][4], Al[2][4];
#pragma unroll
        for (int mt = 0; mt < 2; ++mt) {
            int row = wbase + mt * 16 + lrow_off;
            u32 off = (u32)(row * 144 + (kt * 16 + lcol) * 2);
            ldmatrix_x4(Ah[mt], sb + NB_ZH + off);
            ldmatrix_x4(Al[mt], sb + NB_ZL + off);
        }
#pragma unroll
        for (int nt = 0; nt < 8; ++nt) {
            int tile = kt * 8 + nt;
            uint2 bh = __ldg(reinterpret_cast<const uint2*>(Bh) + tile * 32 + lane);
            uint2 bl = __ldg(reinterpret_cast<const uint2*>(Bl) + tile * 32 + lane);
            u32 bhv[2] = {bh.x, bh.y};
            u32 blv[2] = {bl.x, bl.y};
#pragma unroll
            for (int mt = 0; mt < 2; ++mt) {
                mma_bf16(acc[mt][nt], Ah[mt], bhv);
                mma_bf16(acc[mt][nt], Ah[mt], blv);
                mma_bf16(acc[mt][nt], Al[mt], bhv);
            }
        }
    }
    __syncwarp();  // all lanes done reading zh/zl before in-place overwrite

    int g = lane >> 2, tg = lane & 3;
#pragma unroll
    for (int mt = 0; mt < 2; ++mt) {
        int r0 = wbase + mt * 16 + g;
        int r1 = r0 + 8;
#pragma unroll
        for (int nt = 0; nt < 8; ++nt) {
            int c0 = nt * 8 + 2 * tg;
            float b0 = __ldg(bias + c0), b1v = __ldg(bias + c0 + 1);
            float v0 = fmaxf(acc[mt][nt][0] + b0, 0.f);
            float v1 = fmaxf(acc[mt][nt][1] + b1v, 0.f);
            float v2 = fmaxf(acc[mt][nt][2] + b0, 0.f);
            float v3 = fmaxf(acc[mt][nt][3] + b1v, 0.f);
            u32 ph, pl;
            split_pair(v0, v1, ph, pl);
            *reinterpret_cast<u32*>(smc + NB_ZH + r0 * 144 + c0 * 2) = ph;
            *reinterpret_cast<u32*>(smc + NB_ZL + r0 * 144 + c0 * 2) = pl;
            split_pair(v2, v3, ph, pl);
            *reinterpret_cast<u32*>(smc + NB_ZH + r1 * 144 + c0 * 2) = ph;
            *reinterpret_cast<u32*>(smc + NB_ZL + r1 * 144 + c0 * 2) = pl;
        }
    }
    __syncwarp();
}

// projection stage: out rows = z @ B, stored to gmem (no bias/relu)
__device__ __forceinline__ void node_stage_proj(
    u32 sb, const u32* Bh, const u32* Bl,
    float* __restrict__ dst, int n0, int N, int wbase, int lane) {
    float acc[2][8][4];
#pragma unroll
    for (int mt = 0; mt < 2; ++mt)
#pragma unroll
        for (int nt = 0; nt < 8; ++nt)
#pragma unroll
            for (int i = 0; i < 4; ++i) acc[mt][nt][i] = 0.f;

    int lrow_off = ((lane >> 3) & 1) * 8 + (lane & 7);
    int lcol = ((lane >> 4) << 3);
#pragma unroll
    for (int kt = 0; kt < 4; ++kt) {
        u32 Ah[2][4], Al[2][4];
#pragma unroll
        for (int mt = 0; mt < 2; ++mt) {
            int row = wbase + mt * 16 + lrow_off;
            u32 off = (u32)(row * 144 + (kt * 16 + lcol) * 2);
            ldmatrix_x4(Ah[mt], sb + NB_ZH + off);
            ldmatrix_x4(Al[mt], sb + NB_ZL + off);
        }
#pragma unroll
        for (int nt = 0; nt < 8; ++nt) {
            int tile = kt * 8 + nt;
            uint2 bh = __ldg(reinterpret_cast<const uint2*>(Bh) + tile * 32 + lane);
            uint2 bl = __ldg(reinterpret_cast<const uint2*>(Bl) + tile * 32 + lane);
            u32 bhv[2] = {bh.x, bh.y};
            u32 blv[2] = {bl.x, bl.y};
#pragma unroll
            for (int mt = 0; mt < 2; ++mt) {
                mma_bf16(acc[mt][nt], Ah[mt], bhv);
                mma_bf16(acc[mt][nt], Ah[mt], blv);
                mma_bf16(acc[mt][nt], Al[mt], bhv);
            }
        }
    }

    int g = lane >> 2, tg = lane & 3;
#pragma unroll
    for (int mt = 0; mt < 2; ++mt) {
        int r0 = wbase + mt * 16 + g;
        int r1 = r0 + 8;
        bool ok0 = (n0 + r0) < N, ok1 = (n0 + r1) < N;
#pragma unroll
        for (int nt = 0; nt < 8; ++nt) {
            int c0 = nt * 8 + 2 * tg;
            if (ok0)
                *reinterpret_cast<float2*>(dst + (size_t)(n0 + r0) * 64 + c0) =
                    make_float2(acc[mt][nt][0], acc[mt][nt][1]);
            if (ok1)
                *reinterpret_cast<float2*>(dst + (size_t)(n0 + r1) * 64 + c0) =
                    make_float2(acc[mt][nt][2], acc[mt][nt][3]);
        }
    }
}

__global__ __launch_bounds__(128) void node_kernel(
    const float* __restrict__ x, const float* __restrict__ b1,
    const float* __restrict__ b2, int N) {
    extern __shared__ char smc[];
    u32 sb = smem_u32(smc);
    int t = threadIdx.x;
    int lane = t & 31, wid = t >> 5;
    int wbase = wid * 32;
    int n0 = blockIdx.x * 128;

    // stage x row t as bf16 hi/lo (zeros if out of range)
    {
        float z[64];
        if (n0 + t < N) {
            const float4* xr =
                reinterpret_cast<const float4*>(x) + (size_t)(n0 + t) * 16;
#pragma unroll
            for (int i = 0; i < 16; ++i) {
                float4 v = __ldcs(xr + i);
                z[4 * i] = v.x; z[4 * i + 1] = v.y;
                z[4 * i + 2] = v.z; z[4 * i + 3] = v.w;
            }
        } else {
#pragma unroll
            for (int i = 0; i < 64; ++i) z[i] = 0.f;
        }
        u32* zh = reinterpret_cast<u32*>(smc + NB_ZH + t * 144);
        u32* zl = reinterpret_cast<u32*>(smc + NB_ZL + t * 144);
#pragma unroll
        for (int c = 0; c < 32; ++c) {
            u32 ph, pl;
            split_pair(z[2 * c], z[2 * c + 1], ph, pl);
            zh[c] = ph;
            zl[c] = pl;
        }
    }
    __syncwarp();

    node_stage_relu(smc, sb, g_Fh[0], g_Fl[0], b1, wbase, lane);
    node_stage_relu(smc, sb, g_Fh[1], g_Fl[1], b2, wbase, lane);
    node_stage_proj(sb, g_Fh[2], g_Fl[2], g_p, n0, N, wbase, lane);
    node_stage_proj(sb, g_Fh[3], g_Fl[3], g_q, n0, N, wbase, lane);
}

// ------------------------------------------------------------ edge stage ----
// smem bytes: BFH 0 (8K), BFL 8192 (8K), WM2 16384 (256), BC 16640 (256),
//   SRC 16896 (512), DST 17408 (512), U 17920 (36864: zh[128][72]bf16 +
//   zl[128][72]bf16, later reused as pq[128][68]f32)  -> total 54784
#define EB_BFH  0
#define EB_BFL  8192
#define EB_WM2  16384
#define EB_BC   16640
#define EB_SRC  16896
#define EB_DST  17408
#define EB_U    17920
#define EB_ZL   (EB_U + 18432)
#define EDGE_SMEM_BYTES 54784

__global__ __launch_bounds__(128, 4) void edge_kernel(
    const float* __restrict__ ea, const float* __restrict__ te,
    const int* __restrict__ src, const int* __restrict__ dst,
    const float* __restrict__ Wm2, const float* __restrict__ bm2,
    float* __restrict__ out, int E) {
    extern __shared__ char smc[];
    float* smf = reinterpret_cast<float*>(smc);
    int t = threadIdx.x;
    int lane = t & 31, wid = t >> 5;
    int wbase = wid * 32;
    u32 sb = smem_u32(smc);

    // stage B fragments, wm2, bc, indices
    for (int i = t; i < 512; i += 128) {
        reinterpret_cast<uint4*>(smc + EB_BFH)[i] =
            reinterpret_cast<const uint4*>(g_Bfh)[i];
        reinterpret_cast<uint4*>(smc + EB_BFL)[i] =
            reinterpret_cast<const uint4*>(g_Bfl)[i];
    }
    if (t < 64) {
        smf[EB_WM2 / 4 + t] = Wm2[t];
        smf[EB_BC / 4 + t]  = g_bc[t];
    }
    int e0 = blockIdx.x * 128;
    int e = e0 + t;
    bool valid = e < E;
    reinterpret_cast<int*>(smc + EB_SRC)[t] = valid ? src[e] : 0;
    reinterpret_cast<int*>(smc + EB_DST)[t] = valid ? dst[e] : 0;

    // stage z row (bf16 hi/lo split), rows stride 144B (72 bf16)
    {
        float z[64];
        if (valid) {
            const float4* er = reinterpret_cast<const float4*>(ea) + (size_t)e * 8;
            const float4* tr = reinterpret_cast<const float4*>(te) + (size_t)e * 8;
#pragma unroll
            for (int i = 0; i < 8; ++i) {
                float4 v = er[i];
                z[4 * i] = v.x; z[4 * i + 1] = v.y;
                z[4 * i + 2] = v.z; z[4 * i + 3] = v.w;
                float4 u = tr[i];
                z[32 + 4 * i] = u.x; z[33 + 4 * i] = u.y;
                z[34 + 4 * i] = u.z; z[35 + 4 * i] = u.w;
            }
        } else {
#pragma unroll
            for (int i = 0; i < 64; ++i) z[i] = 0.f;
        }
        u32* zh = reinterpret_cast<u32*>(smc + EB_U + t * 144);
        u32* zl = reinterpret_cast<u32*>(smc + EB_ZL + t * 144);
#pragma unroll
        for (int c = 0; c < 32; ++c) {
            u32 ph, pl;
            split_pair(z[2 * c], z[2 * c + 1], ph, pl);
            zh[c] = ph;
            zl[c] = pl;
        }
    }
    __syncthreads();

    // MMA phase: acc[mt][nt][4] over 3 split terms
    float acc[2][8][4];
#pragma unroll
    for (int mt = 0; mt < 2; ++mt)
#pragma unroll
        for (int nt = 0; nt < 8; ++nt)
#pragma unroll
            for (int i = 0; i < 4; ++i) acc[mt][nt][i] = 0.f;

    {
        int lrow_off = ((lane >> 3) & 1) * 8 + (lane & 7);
        int lcol = ((lane >> 4) << 3);
#pragma unroll
        for (int kt = 0; kt < 4; ++kt) {
            u32 Ah[2][4], Al[2][4];
#pragma unroll
            for (int mt = 0; mt < 2; ++mt) {
                int row = wbase + mt * 16 + lrow_off;
                u32 byteoff = (u32)(row * 144 + (kt * 16 + lcol) * 2);
                ldmatrix_x4(Ah[mt], sb + EB_U + byteoff);
                ldmatrix_x4(Al[mt], sb + EB_ZL + byteoff);
            }
#pragma unroll
            for (int nt = 0; nt < 8; ++nt) {
                int tile = kt * 8 + nt;
                uint2 bh = *reinterpret_cast<const uint2*>(
                    smc + EB_BFH + (tile * 32 + lane) * 8);
                uint2 bl = *reinterpret_cast<const uint2*>(
                    smc + EB_BFL + (tile * 32 + lane) * 8);
                u32 bhv[2] = {bh.x, bh.y};
                u32 blv[2] = {bl.x, bl.y};
#pragma unroll
                for (int mt = 0; mt < 2; ++mt) {
                    mma_bf16(acc[mt][nt], Ah[mt], bhv);
                    mma_bf16(acc[mt][nt], Ah[mt], blv);
                    mma_bf16(acc[mt][nt], Al[mt], bhv);
                }
            }
        }
    }
    __syncthreads();  // all warps done reading zh/zl; U region reused as pq

    // cooperative gather: pq[r] = p[src[r]] + q[dst[r]] + bc  (128B granular)
    {
        const int* ss = reinterpret_cast<const int*>(smc + EB_SRC);
        const int* dd = reinterpret_cast<const int*>(smc + EB_DST);
        const float4* bc4 = reinterpret_cast<const float4*>(smc + EB_BC);
        float* pqs = smf + EB_U / 4;
#pragma unroll
        for (int it = 0; it < 16; ++it) {
            int id = it * 128 + t;
            int r = id >> 4, s = id & 15;
            float4 pv = __ldg(reinterpret_cast<const float4*>(
                                  g_p + (size_t)ss[r] * 64) + s);
            float4 qv = __ldg(reinterpret_cast<const float4*>(
                                  g_q + (size_t)dd[r] * 64) + s);
            float4 bcv = bc4[s];
            float4 o;
            o.x = pv.x + qv.x + bcv.x; o.y = pv.y + qv.y + bcv.y;
            o.z = pv.z + qv.z + bcv.z; o.w = pv.w + qv.w + bcv.w;
            reinterpret_cast<float4*>(pqs + r * 68)[s] = o;
        }
    }
    __syncthreads();

    // epilogue: out[row] = relu(acc + pq) . wm2 + bm2, quad-reduced
    {
        const float* pqs = smf + EB_U / 4;
        const float* wms = smf + EB_WM2 / 4;
        int g = lane >> 2, tg = lane & 3;
        float bm2v = __ldg(bm2);
#pragma unroll
        for (int mt = 0; mt < 2; ++mt) {
            int r0 = wbase + mt * 16 + g;
            int r1 = r0 + 8;
            float sum0 = 0.f, sum1 = 0.f;
#pragma unroll
            for (int nt = 0; nt < 8; ++nt) {
                int c0 = nt * 8 + 2 * tg;
                float2 w  = *reinterpret_cast<const float2*>(wms + c0);
                float2 p0 = *reinterpret_cast<const float2*>(pqs + r0 * 68 + c0);
                float2 p1 = *reinterpret_cast<const float2*>(pqs + r1 * 68 + c0);
                sum0 = fmaf(fmaxf(acc[mt][nt][0] + p0.x, 0.f), w.x, sum0);
                sum0 = fmaf(fmaxf(acc[mt][nt][1] + p0.y, 0.f), w.y, sum0);
                sum1 = fmaf(fmaxf(acc[mt][nt][2] + p1.x, 0.f), w.x, sum1);
                sum1 = fmaf(fmaxf(acc[mt][nt][3] + p1.y, 0.f), w.y, sum1);
            }
            sum0 += __shfl_xor_sync(0xFFFFFFFFu, sum0, 1);
            sum0 += __shfl_xor_sync(0xFFFFFFFFu, sum0, 2);
            sum1 += __shfl_xor_sync(0xFFFFFFFFu, sum1, 1);
            sum1 += __shfl_xor_sync(0xFFFFFFFFu, sum1, 2);
            if (tg == 0) {
                if (e0 + r0 < E) out[e0 + r0] = sum0 + bm2v;
                if (e0 + r1 < E) out[e0 + r1] = sum1 + bm2v;
            }
        }
    }
}

// ------------------------------------------------------------ launch --------
extern "C" void kernel_launch(void* const* d_in, const int* in_sizes, int n_in,
                              void* d_out, int out_size) {
    const float* x   = (const float*)d_in[0];
    const int*   src = (const int*)d_in[1];
    const int*   dst = (const int*)d_in[2];
    const float* ea  = (const float*)d_in[3];
    const float* te  = (const float*)d_in[4];
    const float* W1  = (const float*)d_in[5];
    const float* b1  = (const float*)d_in[6];
    const float* W2  = (const float*)d_in[7];
    const float* b2  = (const float*)d_in[8];
    const float* We  = (const float*)d_in[9];
    const float* be  = (const float*)d_in[10];
    const float* Wm1 = (const float*)d_in[11];
    const float* bm1 = (const float*)d_in[12];
    const float* Wm2 = (const float*)d_in[13];
    const float* bm2 = (const float*)d_in[14];
    float* out = (float*)d_out;

    int N = in_sizes[0] / 64;
    int E = in_sizes[1];

    static bool attrs_set = false;
    if (!attrs_set) {
        cudaFuncSetAttribute(node_kernel,
                             cudaFuncAttributeMaxDynamicSharedMemorySize,
                             NODE_SMEM_BYTES);
        cudaFuncSetAttribute(edge_kernel,
                             cudaFuncAttributeMaxDynamicSharedMemorySize,
                             EDGE_SMEM_BYTES);
        attrs_set = true;
    }

    prep_kernel<<<2, 256>>>(We, be, Wm1, bm1, W1, W2);
    node_kernel<<<(N + 127) / 128, 128, NODE_SMEM_BYTES>>>(x, b1, b2, N);
    edge_kernel<<<(E + 127) / 128, 128, EDGE_SMEM_BYTES>>>(ea, te, src, dst,
                                                           Wm2, bm2, out, E);
}

// round 9
// speedup vs baseline: 2.6167x; 1.1257x over previous
#include <cuda_runtime.h>
#include <cstdint>

// ----------------------------------------------------------------------------
// TGAT edge classifier.
//   prep (2 blocks): Wz = [We @ Wm1[128:192] ; Wm1[192:224]], bc, bf16 hi/lo
//     mma.sync B fragments for Wz, W1, W2, A1, A2.
//   node: 4 chained 64x64 GEMMs per 128-row block via mma.sync bf16x2-split,
//     warp-local pipeline (validated R8).
//   edge: cp.async-prefetched p/q gather overlapped with mma.sync bf16x2-split
//     z @ Wz; epilogue relu(.)·Wm2.
// ----------------------------------------------------------------------------

#define N_CAP 100000
#define H 64

typedef unsigned long long u64;
typedef uint32_t u32;

__device__ float g_p[N_CAP * H];
__device__ float g_q[N_CAP * H];
__device__ float g_Wz[H * H];     // [k][n] fp32
__device__ float g_bc[H];
__device__ __align__(16) u32 g_Bfh[2048];      // edge Wz fragments hi
__device__ __align__(16) u32 g_Bfl[2048];      // edge Wz fragments lo
__device__ __align__(16) u32 g_Fh[4][2048];    // node W1,W2,A1,A2 frags hi
__device__ __align__(16) u32 g_Fl[4][2048];    // node frags lo

// ---------------------------------------------------------- PTX helpers -----
__device__ __forceinline__ u32 smem_u32(const void* p) {
    u32 a;
    asm("{ .reg .u64 t; cvta.to.shared.u64 t, %1; cvt.u32.u64 %0, t; }"
        : "=r"(a) : "l"(p));
    return a;
}
// bf16x2 = {hi half = bf16(h), lo half = bf16(l)}
__device__ __forceinline__ u32 bf2(float h, float l) {
    u32 r;
    asm("cvt.rn.bf16x2.f32 %0, %1, %2;" : "=r"(r) : "f"(h), "f"(l));
    return r;
}
__device__ __forceinline__ void ldmatrix_x4(u32* r, u32 addr) {
    asm volatile(
        "ldmatrix.sync.aligned.m8n8.x4.shared.b16 {%0,%1,%2,%3}, [%4];"
        : "=r"(r[0]), "=r"(r[1]), "=r"(r[2]), "=r"(r[3]) : "r"(addr));
}
__device__ __forceinline__ void mma_bf16(float* c, const u32* a, const u32* b) {
    asm volatile(
        "mma.sync.aligned.m16n8k16.row.col.f32.bf16.bf16.f32 "
        "{%0,%1,%2,%3}, {%4,%5,%6,%7}, {%8,%9}, {%0,%1,%2,%3};"
        : "+f"(c[0]), "+f"(c[1]), "+f"(c[2]), "+f"(c[3])
        : "r"(a[0]), "r"(a[1]), "r"(a[2]), "r"(a[3]), "r"(b[0]), "r"(b[1]));
}
__device__ __forceinline__ void cp_async16(u32 dst, const float* src) {
    u64 g = (u64)__cvta_generic_to_global(src);
    asm volatile("cp.async.cg.shared.global [%0], [%1], 16;"
                 :: "r"(dst), "l"(g) : "memory");
}
#define CP_COMMIT() asm volatile("cp.async.commit_group;" ::: "memory")
#define CP_WAIT0()  asm volatile("cp.async.wait_group 0;" ::: "memory")

// split a float pair into bf16 hi and lo packed words
__device__ __forceinline__ void split_pair(float v0, float v1, u32& ph, u32& pl) {
    ph = bf2(v1, v0);
    float h0 = __uint_as_float(ph << 16);
    float h1 = __uint_as_float(ph & 0xFFFF0000u);
    pl = bf2(v1 - h1, v0 - h0);
}

// ---------------------------------------------------------------- prep ------
__global__ __launch_bounds__(256) void prep_kernel(
    const float* __restrict__ We, const float* __restrict__ be,
    const float* __restrict__ Wm1, const float* __restrict__ bm1,
    const float* __restrict__ W1, const float* __restrict__ W2) {
    int t = threadIdx.x;

    if (blockIdx.x == 1) {
        const float* mats[4] = {W1, W2, Wm1, Wm1 + 64 * 64};
#pragma unroll
        for (int m = 0; m < 4; ++m) {
            const float* M = mats[m];
            for (int idx = t; idx < 2048; idx += 256) {
                int reg  = idx & 1;
                int lane = (idx >> 1) & 31;
                int tile = idx >> 6;           // kt*8 + nt
                int kt = tile >> 3, nt = tile & 7;
                int g = lane >> 2, tg = lane & 3;
                int n = nt * 8 + g;
                int k0 = kt * 16 + 2 * tg + reg * 8;
                u32 ph, pl;
                split_pair(M[k0 * 64 + n], M[(k0 + 1) * 64 + n], ph, pl);
                g_Fh[m][idx] = ph;
                g_Fl[m][idx] = pl;
            }
        }
        return;
    }

    __shared__ float sWe[2048];
    __shared__ float sA3[4096];

    for (int i = t; i < 512; i += 256)
        reinterpret_cast<float4*>(sWe)[i] = reinterpret_cast<const float4*>(We)[i];
    for (int i = t; i < 1024; i += 256)
        reinterpret_cast<float4*>(sA3)[i] =
            reinterpret_cast<const float4*>(Wm1 + 128 * 64)[i];
    __syncthreads();

#pragma unroll
    for (int u = 0; u < 8; ++u) {
        int idx = u * 256 + t;
        int i = idx >> 6, j = idx & 63;
        float s = 0.f;
#pragma unroll 8
        for (int k = 0; k < 64; ++k)
            s = fmaf(sWe[i * 64 + k], sA3[k * 64 + j], s);
        g_Wz[idx] = s;
    }
    for (int i = t; i < 2048; i += 256)
        g_Wz[2048 + i] = Wm1[192 * 64 + i];
    if (t < 64) {
        float s = bm1[t];
#pragma unroll 8
        for (int k = 0; k < 64; ++k)
            s = fmaf(be[k], sA3[k * 64 + t], s);
        g_bc[t] = s;
    }
    __syncthreads();

    for (int idx = t; idx < 2048; idx += 256) {
        int reg  = idx & 1;
        int lane = (idx >> 1) & 31;
        int tile = idx >> 6;
        int kt = tile >> 3, nt = tile & 7;
        int g = lane >> 2, tg = lane & 3;
        int n = nt * 8 + g;
        int k0 = kt * 16 + 2 * tg + reg * 8;
        u32 ph, pl;
        split_pair(g_Wz[k0 * 64 + n], g_Wz[(k0 + 1) * 64 + n], ph, pl);
        g_Bfh[idx] = ph;
        g_Bfl[idx] = pl;
    }
}

// ------------------------------------------------------------ node stage ----
#define NB_ZH 0
#define NB_ZL 18432
#define NODE_SMEM_BYTES 36864

__device__ __forceinline__ void node_stage_relu(
    char* smc, u32 sb, const u32* Bh, const u32* Bl,
    const float* __restrict__ bias, int wbase, int lane) {
    float acc[2][8][4];
#pragma unroll
    for (int mt = 0; mt < 2; ++mt)
#pragma unroll
        for (int nt = 0; nt < 8; ++nt)
#pragma unroll
            for (int i = 0; i < 4; ++i) acc[mt][nt][i] = 0.f;

    int lrow_off = ((lane >> 3) & 1) * 8 + (lane & 7);
    int lcol = ((lane >> 4) << 3);
#pragma unroll
    for (int kt = 0; kt < 4; ++kt) {
        u32 Ah[2][4], Al[2][4];
#pragma unroll
        for (int mt = 0; mt < 2; ++mt) {
            int row = wbase + mt * 16 + lrow_off;
            u32 off = (u32)(row * 144 + (kt * 16 + lcol) * 2);
            ldmatrix_x4(Ah[mt], sb + NB_ZH + off);
            ldmatrix_x4(Al[mt], sb + NB_ZL + off);
        }
#pragma unroll
        for (int nt = 0; nt < 8; ++nt) {
            int tile = kt * 8 + nt;
            uint2 bh = __ldg(reinterpret_cast<const uint2*>(Bh) + tile * 32 + lane);
            uint2 bl = __ldg(reinterpret_cast<const uint2*>(Bl) + tile * 32 + lane);
            u32 bhv[2] = {bh.x, bh.y};
            u32 blv[2] = {bl.x, bl.y};
#pragma unroll
            for (int mt = 0; mt < 2; ++mt) {
                mma_bf16(acc[mt][nt], Ah[mt], bhv);
                mma_bf16(acc[mt][nt], Ah[mt], blv);
                mma_bf16(acc[mt][nt], Al[mt], bhv);
            }
        }
    }
    __syncwarp();

    int g = lane >> 2, tg = lane & 3;
#pragma unroll
    for (int mt = 0; mt < 2; ++mt) {
        int r0 = wbase + mt * 16 + g;
        int r1 = r0 + 8;
#pragma unroll
        for (int nt = 0; nt < 8; ++nt) {
            int c0 = nt * 8 + 2 * tg;
            float b0 = __ldg(bias + c0), b1v = __ldg(bias + c0 + 1);
            float v0 = fmaxf(acc[mt][nt][0] + b0, 0.f);
            float v1 = fmaxf(acc[mt][nt][1] + b1v, 0.f);
            float v2 = fmaxf(acc[mt][nt][2] + b0, 0.f);
            float v3 = fmaxf(acc[mt][nt][3] + b1v, 0.f);
            u32 ph, pl;
            split_pair(v0, v1, ph, pl);
            *reinterpret_cast<u32*>(smc + NB_ZH + r0 * 144 + c0 * 2) = ph;
            *reinterpret_cast<u32*>(smc + NB_ZL + r0 * 144 + c0 * 2) = pl;
            split_pair(v2, v3, ph, pl);
            *reinterpret_cast<u32*>(smc + NB_ZH + r1 * 144 + c0 * 2) = ph;
            *reinterpret_cast<u32*>(smc + NB_ZL + r1 * 144 + c0 * 2) = pl;
        }
    }
    __syncwarp();
}

__device__ __forceinline__ void node_stage_proj(
    u32 sb, const u32* Bh, const u32* Bl,
    float* __restrict__ dst, int n0, int N, int wbase, int lane) {
    float acc[2][8][4];
#pragma unroll
    for (int mt = 0; mt < 2; ++mt)
#pragma unroll
        for (int nt = 0; nt < 8; ++nt)
#pragma unroll
            for (int i = 0; i < 4; ++i) acc[mt][nt][i] = 0.f;

    int lrow_off = ((lane >> 3) & 1) * 8 + (lane & 7);
    int lcol = ((lane >> 4) << 3);
#pragma unroll
    for (int kt = 0; kt < 4; ++kt) {
        u32 Ah[2][4], Al[2][4];
#pragma unroll
        for (int mt = 0; mt < 2; ++mt) {
            int row = wbase + mt * 16 + lrow_off;
            u32 off = (u32)(row * 144 + (kt * 16 + lcol) * 2);
            ldmatrix_x4(Ah[mt], sb + NB_ZH + off);
            ldmatrix_x4(Al[mt], sb + NB_ZL + off);
        }
#pragma unroll
        for (int nt = 0; nt < 8; ++nt) {
            int tile = kt * 8 + nt;
            uint2 bh = __ldg(reinterpret_cast<const uint2*>(Bh) + tile * 32 + lane);
            uint2 bl = __ldg(reinterpret_cast<const uint2*>(Bl) + tile * 32 + lane);
            u32 bhv[2] = {bh.x, bh.y};
            u32 blv[2] = {bl.x, bl.y};
#pragma unroll
            for (int mt = 0; mt < 2; ++mt) {
                mma_bf16(acc[mt][nt], Ah[mt], bhv);
                mma_bf16(acc[mt][nt], Ah[mt], blv);
                mma_bf16(acc[mt][nt], Al[mt], bhv);
            }
        }
    }

    int g = lane >> 2, tg = lane & 3;
#pragma unroll
    for (int mt = 0; mt < 2; ++mt) {
        int r0 = wbase + mt * 16 + g;
        int r1 = r0 + 8;
        bool ok0 = (n0 + r0) < N, ok1 = (n0 + r1) < N;
#pragma unroll
        for (int nt = 0; nt < 8; ++nt) {
            int c0 = nt * 8 + 2 * tg;
            if (ok0)
                *reinterpret_cast<float2*>(dst + (size_t)(n0 + r0) * 64 + c0) =
                    make_float2(acc[mt][nt][0], acc[mt][nt][1]);
            if (ok1)
                *reinterpret_cast<float2*>(dst + (size_t)(n0 + r1) * 64 + c0) =
                    make_float2(acc[mt][nt][2], acc[mt][nt][3]);
        }
    }
}

__global__ __launch_bounds__(128) void node_kernel(
    const float* __restrict__ x, const float* __restrict__ b1,
    const float* __restrict__ b2, int N) {
    extern __shared__ char smc[];
    u32 sb = smem_u32(smc);
    int t = threadIdx.x;
    int lane = t & 31, wid = t >> 5;
    int wbase = wid * 32;
    int n0 = blockIdx.x * 128;

    {
        float z[64];
        if (n0 + t < N) {
            const float4* xr =
                reinterpret_cast<const float4*>(x) + (size_t)(n0 + t) * 16;
#pragma unroll
            for (int i = 0; i < 16; ++i) {
                float4 v = __ldcs(xr + i);
                z[4 * i] = v.x; z[4 * i + 1] = v.y;
                z[4 * i + 2] = v.z; z[4 * i + 3] = v.w;
            }
        } else {
#pragma unroll
            for (int i = 0; i < 64; ++i) z[i] = 0.f;
        }
        u32* zh = reinterpret_cast<u32*>(smc + NB_ZH + t * 144);
        u32* zl = reinterpret_cast<u32*>(smc + NB_ZL + t * 144);
#pragma unroll
        for (int c = 0; c < 32; ++c) {
            u32 ph, pl;
            split_pair(z[2 * c], z[2 * c + 1], ph, pl);
            zh[c] = ph;
            zl[c] = pl;
        }
    }
    __syncwarp();

    node_stage_relu(smc, sb, g_Fh[0], g_Fl[0], b1, wbase, lane);
    node_stage_relu(smc, sb, g_Fh[1], g_Fl[1], b2, wbase, lane);
    node_stage_proj(sb, g_Fh[2], g_Fl[2], g_p, n0, N, wbase, lane);
    node_stage_proj(sb, g_Fh[3], g_Fl[3], g_q, n0, N, wbase, lane);
}

// ------------------------------------------------------------ edge stage ----
// smem bytes: BC 0 (256), WM2 256 (256), SRC 512 (512), DST 1024 (512),
//   ZH 1536 (18432), ZL 19968 (18432), PB 38400 (34816: 128 rows x 68 f32),
//   QB 73216 (34816)  -> total 108032.  2 CTAs/SM.
#define EB_BC   0
#define EB_WM2  256
#define EB_SRC  512
#define EB_DST  1024
#define EB_ZH   1536
#define EB_ZL   19968
#define EB_PB   38400
#define EB_QB   73216
#define EDGE_SMEM_BYTES 108032

__global__ __launch_bounds__(128, 2) void edge_kernel(
    const float* __restrict__ ea, const float* __restrict__ te,
    const int* __restrict__ src, const int* __restrict__ dst,
    const float* __restrict__ Wm2, const float* __restrict__ bm2,
    float* __restrict__ out, int E) {
    extern __shared__ char smc[];
    float* smf = reinterpret_cast<float*>(smc);
    int t = threadIdx.x;
    int lane = t & 31, wid = t >> 5;
    int wbase = wid * 32;
    u32 sb = smem_u32(smc);

    if (t < 64) {
        smf[EB_WM2 / 4 + t] = Wm2[t];
        smf[EB_BC / 4 + t]  = g_bc[t];
    }
    int e0 = blockIdx.x * 128;
    int e = e0 + t;
    bool valid = e < E;
    reinterpret_cast<int*>(smc + EB_SRC)[t] = valid ? src[e] : 0;
    reinterpret_cast<int*>(smc + EB_DST)[t] = valid ? dst[e] : 0;
    __syncthreads();

    // issue cooperative cp.async gather of p/q rows (overlaps with z staging
    // and the whole MMA phase below).  128B-granular per quad-row.
    {
        const int* ss = reinterpret_cast<const int*>(smc + EB_SRC);
        const int* dd = reinterpret_cast<const int*>(smc + EB_DST);
#pragma unroll
        for (int it = 0; it < 16; ++it) {
            int id = it * 128 + t;
            int r = id >> 4, s = id & 15;
            u32 soff = (u32)(r * 272 + s * 16);
            cp_async16(sb + EB_PB + soff, g_p + (size_t)ss[r] * 64 + s * 4);
            cp_async16(sb + EB_QB + soff, g_q + (size_t)dd[r] * 64 + s * 4);
        }
        CP_COMMIT();
    }

    // stage z row (bf16 hi/lo split), rows stride 144B (72 bf16)
    {
        float z[64];
        if (valid) {
            const float4* er = reinterpret_cast<const float4*>(ea) + (size_t)e * 8;
            const float4* tr = reinterpret_cast<const float4*>(te) + (size_t)e * 8;
#pragma unroll
            for (int i = 0; i < 8; ++i) {
                float4 v = __ldcs(er + i);
                z[4 * i] = v.x; z[4 * i + 1] = v.y;
                z[4 * i + 2] = v.z; z[4 * i + 3] = v.w;
                float4 u = __ldcs(tr + i);
                z[32 + 4 * i] = u.x; z[33 + 4 * i] = u.y;
                z[34 + 4 * i] = u.z; z[35 + 4 * i] = u.w;
            }
        } else {
#pragma unroll
            for (int i = 0; i < 64; ++i) z[i] = 0.f;
        }
        u32* zh = reinterpret_cast<u32*>(smc + EB_ZH + t * 144);
        u32* zl = reinterpret_cast<u32*>(smc + EB_ZL + t * 144);
#pragma unroll
        for (int c = 0; c < 32; ++c) {
            u32 ph, pl;
            split_pair(z[2 * c], z[2 * c + 1], ph, pl);
            zh[c] = ph;
            zl[c] = pl;
        }
    }
    __syncthreads();

    // MMA phase (B fragments via __ldg, L1-resident)
    float acc[2][8][4];
#pragma unroll
    for (int mt = 0; mt < 2; ++mt)
#pragma unroll
        for (int nt = 0; nt < 8; ++nt)
#pragma unroll
            for (int i = 0; i < 4; ++i) acc[mt][nt][i] = 0.f;

    {
        int lrow_off = ((lane >> 3) & 1) * 8 + (lane & 7);
        int lcol = ((lane >> 4) << 3);
#pragma unroll
        for (int kt = 0; kt < 4; ++kt) {
            u32 Ah[2][4], Al[2][4];
#pragma unroll
            for (int mt = 0; mt < 2; ++mt) {
                int row = wbase + mt * 16 + lrow_off;
                u32 byteoff = (u32)(row * 144 + (kt * 16 + lcol) * 2);
                ldmatrix_x4(Ah[mt], sb + EB_ZH + byteoff);
                ldmatrix_x4(Al[mt], sb + EB_ZL + byteoff);
            }
#pragma unroll
            for (int nt = 0; nt < 8; ++nt) {
                int tile = kt * 8 + nt;
                uint2 bh = __ldg(reinterpret_cast<const uint2*>(g_Bfh) +
                                 tile * 32 + lane);
                uint2 bl = __ldg(reinterpret_cast<const uint2*>(g_Bfl) +
                                 tile * 32 + lane);
                u32 bhv[2] = {bh.x, bh.y};
                u32 blv[2] = {bl.x, bl.y};
#pragma unroll
                for (int mt = 0; mt < 2; ++mt) {
                    mma_bf16(acc[mt][nt], Ah[mt], bhv);
                    mma_bf16(acc[mt][nt], Ah[mt], blv);
                    mma_bf16(acc[mt][nt], Al[mt], bhv);
                }
            }
        }
    }

    // wait for gathered p/q (should already be resident), then epilogue
    CP_WAIT0();
    __syncthreads();

    {
        const float* pb = smf + EB_PB / 4;
        const float* qb = smf + EB_QB / 4;
        const float* bcp = smf + EB_BC / 4;
        const float* wms = smf + EB_WM2 / 4;
        int g = lane >> 2, tg = lane & 3;
        float bm2v = __ldg(bm2);
#pragma unroll
        for (int mt = 0; mt < 2; ++mt) {
            int r0 = wbase + mt * 16 + g;
            int r1 = r0 + 8;
            float sum0 = 0.f, sum1 = 0.f;
#pragma unroll
            for (int nt = 0; nt < 8; ++nt) {
                int c0 = nt * 8 + 2 * tg;
                float2 w   = *reinterpret_cast<const float2*>(wms + c0);
                float2 bc2 = *reinterpret_cast<const float2*>(bcp + c0);
                float2 p0 = *reinterpret_cast<const float2*>(pb + r0 * 68 + c0);
                float2 q0 = *reinterpret_cast<const float2*>(qb + r0 * 68 + c0);
                float2 p1 = *reinterpret_cast<const float2*>(pb + r1 * 68 + c0);
                float2 q1 = *reinterpret_cast<const float2*>(qb + r1 * 68 + c0);
                sum0 = fmaf(fmaxf(acc[mt][nt][0] + p0.x + q0.x + bc2.x, 0.f), w.x, sum0);
                sum0 = fmaf(fmaxf(acc[mt][nt][1] + p0.y + q0.y + bc2.y, 0.f), w.y, sum0);
                sum1 = fmaf(fmaxf(acc[mt][nt][2] + p1.x + q1.x + bc2.x, 0.f), w.x, sum1);
                sum1 = fmaf(fmaxf(acc[mt][nt][3] + p1.y + q1.y + bc2.y, 0.f), w.y, sum1);
            }
            sum0 += __shfl_xor_sync(0xFFFFFFFFu, sum0, 1);
            sum0 += __shfl_xor_sync(0xFFFFFFFFu, sum0, 2);
            sum1 += __shfl_xor_sync(0xFFFFFFFFu, sum1, 1);
            sum1 += __shfl_xor_sync(0xFFFFFFFFu, sum1, 2);
            if (tg == 0) {
                if (e0 + r0 < E) out[e0 + r0] = sum0 + bm2v;
                if (e0 + r1 < E) out[e0 + r1] = sum1 + bm2v;
            }
        }
    }
}

// ------------------------------------------------------------ launch --------
extern "C" void kernel_launch(void* const* d_in, const int* in_sizes, int n_in,
                              void* d_out, int out_size) {
    const float* x   = (const float*)d_in[0];
    const int*   src = (const int*)d_in[1];
    const int*   dst = (const int*)d_in[2];
    const float* ea  = (const float*)d_in[3];
    const float* te  = (const float*)d_in[4];
    const float* W1  = (const float*)d_in[5];
    const float* b1  = (const float*)d_in[6];
    const float* W2  = (const float*)d_in[7];
    const float* b2  = (const float*)d_in[8];
    const float* We  = (const float*)d_in[9];
    const float* be  = (const float*)d_in[10];
    const float* Wm1 = (const float*)d_in[11];
    const float* bm1 = (const float*)d_in[12];
    const float* Wm2 = (const float*)d_in[13];
    const float* bm2 = (const float*)d_in[14];
    float* out = (float*)d_out;

    int N = in_sizes[0] / 64;
    int E = in_sizes[1];

    static bool attrs_set = false;
    if (!attrs_set) {
        cudaFuncSetAttribute(node_kernel,
                             cudaFuncAttributeMaxDynamicSharedMemorySize,
                             NODE_SMEM_BYTES);
        cudaFuncSetAttribute(edge_kernel,
                             cudaFuncAttributeMaxDynamicSharedMemorySize,
                             EDGE_SMEM_BYTES);
        attrs_set = true;
    }

    prep_kernel<<<2, 256>>>(We, be, Wm1, bm1, W1, W2);
    node_kernel<<<(N + 127) / 128, 128, NODE_SMEM_BYTES>>>(x, b1, b2, N);
    edge_kernel<<<(E + 127) / 128, 128, EDGE_SMEM_BYTES>>>(ea, te, src, dst,
                                                           Wm2, bm2, out, E);
}

// round 12
// speedup vs baseline: 3.3026x; 1.2621x over previous
#include <cuda_runtime.h>
#include <cuda_fp16.h>
#include <cstdint>

// ----------------------------------------------------------------------------
// TGAT edge classifier.
//   prep (2 blocks): Wz = [We @ Wm1[128:192] ; Wm1[192:224]], bc, bf16 hi/lo
//     mma.sync B fragments for Wz, W1, W2, A1, A2.
//   node: 4 chained 64x64 GEMMs per 128-row block via mma.sync bf16x2-split,
//     warp-local pipeline; p/q projections stored as fp16 (halves gather
//     traffic in the edge stage).
//   edge: cp.async-prefetched fp16 p/q gather overlapped with mma.sync
//     bf16x2-split z @ Wz; epilogue relu(.)·Wm2.  3 CTAs/SM.
// ----------------------------------------------------------------------------

#define N_CAP 100000
#define H 64

typedef unsigned long long u64;
typedef uint32_t u32;

__device__ u32 g_p[N_CAP * 32];   // fp16 p table: [n][32] half2-packed
__device__ u32 g_q[N_CAP * 32];   // fp16 q table
__device__ float g_Wz[H * H];     // [k][n] fp32
__device__ float g_bc[H];
__device__ __align__(16) u32 g_Bfh[2048];      // edge Wz fragments hi
__device__ __align__(16) u32 g_Bfl[2048];      // edge Wz fragments lo
__device__ __align__(16) u32 g_Fh[4][2048];    // node W1,W2,A1,A2 frags hi
__device__ __align__(16) u32 g_Fl[4][2048];    // node frags lo

// ---------------------------------------------------------- PTX helpers -----
__device__ __forceinline__ u32 smem_u32(const void* p) {
    u32 a;
    asm("{ .reg .u64 t; cvta.to.shared.u64 t, %1; cvt.u32.u64 %0, t; }"
        : "=r"(a) : "l"(p));
    return a;
}
// bf16x2 = {hi half = bf16(h), lo half = bf16(l)}
__device__ __forceinline__ u32 bf2(float h, float l) {
    u32 r;
    asm("cvt.rn.bf16x2.f32 %0, %1, %2;" : "=r"(r) : "f"(h), "f"(l));
    return r;
}
__device__ __forceinline__ void ldmatrix_x4(u32* r, u32 addr) {
    asm volatile(
        "ldmatrix.sync.aligned.m8n8.x4.shared.b16 {%0,%1,%2,%3}, [%4];"
        : "=r"(r[0]), "=r"(r[1]), "=r"(r[2]), "=r"(r[3]) : "r"(addr));
}
__device__ __forceinline__ void mma_bf16(float* c, const u32* a, const u32* b) {
    asm volatile(
        "mma.sync.aligned.m16n8k16.row.col.f32.bf16.bf16.f32 "
        "{%0,%1,%2,%3}, {%4,%5,%6,%7}, {%8,%9}, {%0,%1,%2,%3};"
        : "+f"(c[0]), "+f"(c[1]), "+f"(c[2]), "+f"(c[3])
        : "r"(a[0]), "r"(a[1]), "r"(a[2]), "r"(a[3]), "r"(b[0]), "r"(b[1]));
}
__device__ __forceinline__ void cp_async16(u32 dst, const void* src) {
    u64 g = (u64)__cvta_generic_to_global(src);
    asm volatile("cp.async.cg.shared.global [%0], [%1], 16;"
                 :: "r"(dst), "l"(g) : "memory");
}
#define CP_COMMIT() asm volatile("cp.async.commit_group;" ::: "memory")
#define CP_WAIT0()  asm volatile("cp.async.wait_group 0;" ::: "memory")

// split a float pair into bf16 hi and lo packed words
__device__ __forceinline__ void split_pair(float v0, float v1, u32& ph, u32& pl) {
    ph = bf2(v1, v0);
    float h0 = __uint_as_float(ph << 16);
    float h1 = __uint_as_float(ph & 0xFFFF0000u);
    pl = bf2(v1 - h1, v0 - h0);
}

// ---------------------------------------------------------------- prep ------
__global__ __launch_bounds__(256) void prep_kernel(
    const float* __restrict__ We, const float* __restrict__ be,
    const float* __restrict__ Wm1, const float* __restrict__ bm1,
    const float* __restrict__ W1, const float* __restrict__ W2) {
    int t = threadIdx.x;

    if (blockIdx.x == 1) {
        const float* mats[4] = {W1, W2, Wm1, Wm1 + 64 * 64};
#pragma unroll
        for (int m = 0; m < 4; ++m) {
            const float* M = mats[m];
            for (int idx = t; idx < 2048; idx += 256) {
                int reg  = idx & 1;
                int lane = (idx >> 1) & 31;
                int tile = idx >> 6;           // kt*8 + nt
                int kt = tile >> 3, nt = tile & 7;
                int g = lane >> 2, tg = lane & 3;
                int n = nt * 8 + g;
                int k0 = kt * 16 + 2 * tg + reg * 8;
                u32 ph, pl;
                split_pair(M[k0 * 64 + n], M[(k0 + 1) * 64 + n], ph, pl);
                g_Fh[m][idx] = ph;
                g_Fl[m][idx] = pl;
            }
        }
        return;
    }

    __shared__ float sWe[2048];
    __shared__ float sA3[4096];

    for (int i = t; i < 512; i += 256)
        reinterpret_cast<float4*>(sWe)[i] = reinterpret_cast<const float4*>(We)[i];
    for (int i = t; i < 1024; i += 256)
        reinterpret_cast<float4*>(sA3)[i] =
            reinterpret_cast<const float4*>(Wm1 + 128 * 64)[i];
    __syncthreads();

#pragma unroll
    for (int u = 0; u < 8; ++u) {
        int idx = u * 256 + t;
        int i = idx >> 6, j = idx & 63;
        float s = 0.f;
#pragma unroll 8
        for (int k = 0; k < 64; ++k)
            s = fmaf(sWe[i * 64 + k], sA3[k * 64 + j], s);
        g_Wz[idx] = s;
    }
    for (int i = t; i < 2048; i += 256)
        g_Wz[2048 + i] = Wm1[192 * 64 + i];
    if (t < 64) {
        float s = bm1[t];
#pragma unroll 8
        for (int k = 0; k < 64; ++k)
            s = fmaf(be[k], sA3[k * 64 + t], s);
        g_bc[t] = s;
    }
    __syncthreads();

    for (int idx = t; idx < 2048; idx += 256) {
        int reg  = idx & 1;
        int lane = (idx >> 1) & 31;
        int tile = idx >> 6;
        int kt = tile >> 3, nt = tile & 7;
        int g = lane >> 2, tg = lane & 3;
        int n = nt * 8 + g;
        int k0 = kt * 16 + 2 * tg + reg * 8;
        u32 ph, pl;
        split_pair(g_Wz[k0 * 64 + n], g_Wz[(k0 + 1) * 64 + n], ph, pl);
        g_Bfh[idx] = ph;
        g_Bfl[idx] = pl;
    }
}

// ------------------------------------------------------------ node stage ----
#define NB_ZH 0
#define NB_ZL 18432
#define NODE_SMEM_BYTES 36864

__device__ __forceinline__ void node_stage_relu(
    char* smc, u32 sb, const u32* Bh, const u32* Bl,
    const float* __restrict__ bias, int wbase, int lane) {
    float acc[2][8][4];
#pragma unroll
    for (int mt = 0; mt < 2; ++mt)
#pragma unroll
        for (int nt = 0; nt < 8; ++nt)
#pragma unroll
            for (int i = 0; i < 4; ++i) acc[mt][nt][i] = 0.f;

    int lrow_off = ((lane >> 3) & 1) * 8 + (lane & 7);
    int lcol = ((lane >> 4) << 3);
#pragma unroll
    for (int kt = 0; kt < 4; ++kt) {
        u32 Ah[2][4], Al[2][4];
#pragma unroll
        for (int mt = 0; mt < 2; ++mt) {
            int row = wbase + mt * 16 + lrow_off;
            u32 off = (u32)(row * 144 + (kt * 16 + lcol) * 2);
            ldmatrix_x4(Ah[mt], sb + NB_ZH + off);
            ldmatrix_x4(Al[mt], sb + NB_ZL + off);
        }
#pragma unroll
        for (int nt = 0; nt < 8; ++nt) {
            int tile = kt * 8 + nt;
            uint2 bh = __ldg(reinterpret_cast<const uint2*>(Bh) + tile * 32 + lane);
            uint2 bl = __ldg(reinterpret_cast<const uint2*>(Bl) + tile * 32 + lane);
            u32 bhv[2] = {bh.x, bh.y};
            u32 blv[2] = {bl.x, bl.y};
#pragma unroll
            for (int mt = 0; mt < 2; ++mt) {
                mma_bf16(acc[mt][nt], Ah[mt], bhv);
                mma_bf16(acc[mt][nt], Ah[mt], blv);
                mma_bf16(acc[mt][nt], Al[mt], bhv);
            }
        }
    }
    __syncwarp();

    int g = lane >> 2, tg = lane & 3;
#pragma unroll
    for (int mt = 0; mt < 2; ++mt) {
        int r0 = wbase + mt * 16 + g;
        int r1 = r0 + 8;
#pragma unroll
        for (int nt = 0; nt < 8; ++nt) {
            int c0 = nt * 8 + 2 * tg;
            float b0 = __ldg(bias + c0), b1v = __ldg(bias + c0 + 1);
            float v0 = fmaxf(acc[mt][nt][0] + b0, 0.f);
            float v1 = fmaxf(acc[mt][nt][1] + b1v, 0.f);
            float v2 = fmaxf(acc[mt][nt][2] + b0, 0.f);
            float v3 = fmaxf(acc[mt][nt][3] + b1v, 0.f);
            u32 ph, pl;
            split_pair(v0, v1, ph, pl);
            *reinterpret_cast<u32*>(smc + NB_ZH + r0 * 144 + c0 * 2) = ph;
            *reinterpret_cast<u32*>(smc + NB_ZL + r0 * 144 + c0 * 2) = pl;
            split_pair(v2, v3, ph, pl);
            *reinterpret_cast<u32*>(smc + NB_ZH + r1 * 144 + c0 * 2) = ph;
            *reinterpret_cast<u32*>(smc + NB_ZL + r1 * 144 + c0 * 2) = pl;
        }
    }
    __syncwarp();
}

// projection stage: out rows = z @ B, stored to gmem as packed fp16
__device__ __forceinline__ void node_stage_proj(
    u32 sb, const u32* Bh, const u32* Bl,
    u32* __restrict__ dst, int n0, int N, int wbase, int lane) {
    float acc[2][8][4];
#pragma unroll
    for (int mt = 0; mt < 2; ++mt)
#pragma unroll
        for (int nt = 0; nt < 8; ++nt)
#pragma unroll
            for (int i = 0; i < 4; ++i) acc[mt][nt][i] = 0.f;

    int lrow_off = ((lane >> 3) & 1) * 8 + (lane & 7);
    int lcol = ((lane >> 4) << 3);
#pragma unroll
    for (int kt = 0; kt < 4; ++kt) {
        u32 Ah[2][4], Al[2][4];
#pragma unroll
        for (int mt = 0; mt < 2; ++mt) {
            int row = wbase + mt * 16 + lrow_off;
            u32 off = (u32)(row * 144 + (kt * 16 + lcol) * 2);
            ldmatrix_x4(Ah[mt], sb + NB_ZH + off);
            ldmatrix_x4(Al[mt], sb + NB_ZL + off);
        }
#pragma unroll
        for (int nt = 0; nt < 8; ++nt) {
            int tile = kt * 8 + nt;
            uint2 bh = __ldg(reinterpret_cast<const uint2*>(Bh) + tile * 32 + lane);
            uint2 bl = __ldg(reinterpret_cast<const uint2*>(Bl) + tile * 32 + lane);
            u32 bhv[2] = {bh.x, bh.y};
            u32 blv[2] = {bl.x, bl.y};
#pragma unroll
            for (int mt = 0; mt < 2; ++mt) {
                mma_bf16(acc[mt][nt], Ah[mt], bhv);
                mma_bf16(acc[mt][nt], Ah[mt], blv);
                mma_bf16(acc[mt][nt], Al[mt], bhv);
            }
        }
    }

    int g = lane >> 2, tg = lane & 3;
#pragma unroll
    for (int mt = 0; mt < 2; ++mt) {
        int r0 = wbase + mt * 16 + g;
        int r1 = r0 + 8;
        bool ok0 = (n0 + r0) < N, ok1 = (n0 + r1) < N;
#pragma unroll
        for (int nt = 0; nt < 8; ++nt) {
            int c0 = nt * 8 + 2 * tg;
            if (ok0) {
                __half2 h = __float22half2_rn(
                    make_float2(acc[mt][nt][0], acc[mt][nt][1]));
                dst[(size_t)(n0 + r0) * 32 + (c0 >> 1)] =
                    *reinterpret_cast<u32*>(&h);
            }
            if (ok1) {
                __half2 h = __float22half2_rn(
                    make_float2(acc[mt][nt][2], acc[mt][nt][3]));
                dst[(size_t)(n0 + r1) * 32 + (c0 >> 1)] =
                    *reinterpret_cast<u32*>(&h);
            }
        }
    }
}

__global__ __launch_bounds__(128) void node_kernel(
    const float* __restrict__ x, const float* __restrict__ b1,
    const float* __restrict__ b2, int N) {
    extern __shared__ char smc[];
    u32 sb = smem_u32(smc);
    int t = threadIdx.x;
    int lane = t & 31, wid = t >> 5;
    int wbase = wid * 32;
    int n0 = blockIdx.x * 128;

    {
        float z[64];
        if (n0 + t < N) {
            const float4* xr =
                reinterpret_cast<const float4*>(x) + (size_t)(n0 + t) * 16;
#pragma unroll
            for (int i = 0; i < 16; ++i) {
                float4 v = __ldcs(xr + i);
                z[4 * i] = v.x; z[4 * i + 1] = v.y;
                z[4 * i + 2] = v.z; z[4 * i + 3] = v.w;
            }
        } else {
#pragma unroll
            for (int i = 0; i < 64; ++i) z[i] = 0.f;
        }
        u32* zh = reinterpret_cast<u32*>(smc + NB_ZH + t * 144);
        u32* zl = reinterpret_cast<u32*>(smc + NB_ZL + t * 144);
#pragma unroll
        for (int c = 0; c < 32; ++c) {
            u32 ph, pl;
            split_pair(z[2 * c], z[2 * c + 1], ph, pl);
            zh[c] = ph;
            zl[c] = pl;
        }
    }
    __syncwarp();

    node_stage_relu(smc, sb, g_Fh[0], g_Fl[0], b1, wbase, lane);
    node_stage_relu(smc, sb, g_Fh[1], g_Fl[1], b2, wbase, lane);
    node_stage_proj(sb, g_Fh[2], g_Fl[2], g_p, n0, N, wbase, lane);
    node_stage_proj(sb, g_Fh[3], g_Fl[3], g_q, n0, N, wbase, lane);
}

// ------------------------------------------------------------ edge stage ----
// smem bytes: BC 0 (256), WM2 256 (256), SRC 512 (512), DST 1024 (512),
//   ZH 1536 (18432), ZL 19968 (18432), PB 38400 (18432: 128 rows x 144B fp16),
//   QB 56832 (18432)  -> total 75264.  3 CTAs/SM.
#define EB_BC   0
#define EB_WM2  256
#define EB_SRC  512
#define EB_DST  1024
#define EB_ZH   1536
#define EB_ZL   19968
#define EB_PB   38400
#define EB_QB   56832
#define EDGE_SMEM_BYTES 75264

__global__ __launch_bounds__(128, 3) void edge_kernel(
    const float* __restrict__ ea, const float* __restrict__ te,
    const int* __restrict__ src, const int* __restrict__ dst,
    const float* __restrict__ Wm2, const float* __restrict__ bm2,
    float* __restrict__ out, int E) {
    extern __shared__ char smc[];
    float* smf = reinterpret_cast<float*>(smc);
    int t = threadIdx.x;
    int lane = t & 31, wid = t >> 5;
    int wbase = wid * 32;
    u32 sb = smem_u32(smc);

    if (t < 64) {
        smf[EB_WM2 / 4 + t] = Wm2[t];
        smf[EB_BC / 4 + t]  = g_bc[t];
    }
    int e0 = blockIdx.x * 128;
    int e = e0 + t;
    bool valid = e < E;
    reinterpret_cast<int*>(smc + EB_SRC)[t] = valid ? src[e] : 0;
    reinterpret_cast<int*>(smc + EB_DST)[t] = valid ? dst[e] : 0;
    __syncthreads();

    // cooperative cp.async gather of fp16 p/q rows (128B per row, 8 segs);
    // overlaps z staging + the whole MMA phase below.
    {
        const int* ss = reinterpret_cast<const int*>(smc + EB_SRC);
        const int* dd = reinterpret_cast<const int*>(smc + EB_DST);
#pragma unroll
        for (int it = 0; it < 8; ++it) {
            int id = it * 128 + t;
            int r = id >> 3, s = id & 7;
            u32 soff = (u32)(r * 144 + s * 16);
            cp_async16(sb + EB_PB + soff,
                       reinterpret_cast<const char*>(g_p) +
                           (size_t)ss[r] * 128 + s * 16);
            cp_async16(sb + EB_QB + soff,
                       reinterpret_cast<const char*>(g_q) +
                           (size_t)dd[r] * 128 + s * 16);
        }
        CP_COMMIT();
    }

    // stage z row (bf16 hi/lo split), rows stride 144B (72 bf16)
    {
        float z[64];
        if (valid) {
            const float4* er = reinterpret_cast<const float4*>(ea) + (size_t)e * 8;
            const float4* tr = reinterpret_cast<const float4*>(te) + (size_t)e * 8;
#pragma unroll
            for (int i = 0; i < 8; ++i) {
                float4 v = __ldcs(er + i);
                z[4 * i] = v.x; z[4 * i + 1] = v.y;
                z[4 * i + 2] = v.z; z[4 * i + 3] = v.w;
                float4 u = __ldcs(tr + i);
                z[32 + 4 * i] = u.x; z[33 + 4 * i] = u.y;
                z[34 + 4 * i] = u.z; z[35 + 4 * i] = u.w;
            }
        } else {
#pragma unroll
            for (int i = 0; i < 64; ++i) z[i] = 0.f;
        }
        u32* zh = reinterpret_cast<u32*>(smc + EB_ZH + t * 144);
        u32* zl = reinterpret_cast<u32*>(smc + EB_ZL + t * 144);
#pragma unroll
        for (int c = 0; c < 32; ++c) {
            u32 ph, pl;
            split_pair(z[2 * c], z[2 * c + 1], ph, pl);
            zh[c] = ph;
            zl[c] = pl;
        }
    }
    __syncthreads();

    // MMA phase (B fragments via __ldg, L1-resident)
    float acc[2][8][4];
#pragma unroll
    for (int mt = 0; mt < 2; ++mt)
#pragma unroll
        for (int nt = 0; nt < 8; ++nt)
#pragma unroll
            for (int i = 0; i < 4; ++i) acc[mt][nt][i] = 0.f;

    {
        int lrow_off = ((lane >> 3) & 1) * 8 + (lane & 7);
        int lcol = ((lane >> 4) << 3);
#pragma unroll
        for (int kt = 0; kt < 4; ++kt) {
            u32 Ah[2][4], Al[2][4];
#pragma unroll
            for (int mt = 0; mt < 2; ++mt) {
                int row = wbase + mt * 16 + lrow_off;
                u32 byteoff = (u32)(row * 144 + (kt * 16 + lcol) * 2);
                ldmatrix_x4(Ah[mt], sb + EB_ZH + byteoff);
                ldmatrix_x4(Al[mt], sb + EB_ZL + byteoff);
            }
#pragma unroll
            for (int nt = 0; nt < 8; ++nt) {
                int tile = kt * 8 + nt;
                uint2 bh = __ldg(reinterpret_cast<const uint2*>(g_Bfh) +
                                 tile * 32 + lane);
                uint2 bl = __ldg(reinterpret_cast<const uint2*>(g_Bfl) +
                                 tile * 32 + lane);
                u32 bhv[2] = {bh.x, bh.y};
                u32 blv[2] = {bl.x, bl.y};
#pragma unroll
                for (int mt = 0; mt < 2; ++mt) {
                    mma_bf16(acc[mt][nt], Ah[mt], bhv);
                    mma_bf16(acc[mt][nt], Ah[mt], blv);
                    mma_bf16(acc[mt][nt], Al[mt], bhv);
                }
            }
        }
    }

    // wait for gathered p/q (should already be resident), then epilogue
    CP_WAIT0();
    __syncthreads();

    {
        const float* bcp = smf + EB_BC / 4;
        const float* wms = smf + EB_WM2 / 4;
        int g = lane >> 2, tg = lane & 3;
        float bm2v = __ldg(bm2);
#pragma unroll
        for (int mt = 0; mt < 2; ++mt) {
            int r0 = wbase + mt * 16 + g;
            int r1 = r0 + 8;
            float sum0 = 0.f, sum1 = 0.f;
#pragma unroll
            for (int nt = 0; nt < 8; ++nt) {
                int c0 = nt * 8 + 2 * tg;
                float2 w   = *reinterpret_cast<const float2*>(wms + c0);
                float2 bc2 = *reinterpret_cast<const float2*>(bcp + c0);
                float2 p0 = __half22float2(*reinterpret_cast<const __half2*>(
                    smc + EB_PB + r0 * 144 + c0 * 2));
                float2 q0 = __half22float2(*reinterpret_cast<const __half2*>(
                    smc + EB_QB + r0 * 144 + c0 * 2));
                float2 p1 = __half22float2(*reinterpret_cast<const __half2*>(
                    smc + EB_PB + r1 * 144 + c0 * 2));
                float2 q1 = __half22float2(*reinterpret_cast<const __half2*>(
                    smc + EB_QB + r1 * 144 + c0 * 2));
                sum0 = fmaf(fmaxf(acc[mt][nt][0] + p0.x + q0.x + bc2.x, 0.f), w.x, sum0);
                sum0 = fmaf(fmaxf(acc[mt][nt][1] + p0.y + q0.y + bc2.y, 0.f), w.y, sum0);
                sum1 = fmaf(fmaxf(acc[mt][nt][2] + p1.x + q1.x + bc2.x, 0.f), w.x, sum1);
                sum1 = fmaf(fmaxf(acc[mt][nt][3] + p1.y + q1.y + bc2.y, 0.f), w.y, sum1);
            }
            sum0 += __shfl_xor_sync(0xFFFFFFFFu, sum0, 1);
            sum0 += __shfl_xor_sync(0xFFFFFFFFu, sum0, 2);
            sum1 += __shfl_xor_sync(0xFFFFFFFFu, sum1, 1);
            sum1 += __shfl_xor_sync(0xFFFFFFFFu, sum1, 2);
            if (tg == 0) {
                if (e0 + r0 < E) out[e0 + r0] = sum0 + bm2v;
                if (e0 + r1 < E) out[e0 + r1] = sum1 + bm2v;
            }
        }
    }
}

// ------------------------------------------------------------ launch --------
extern "C" void kernel_launch(void* const* d_in, const int* in_sizes, int n_in,
                              void* d_out, int out_size) {
    const float* x   = (const float*)d_in[0];
    const int*   src = (const int*)d_in[1];
    const int*   dst = (const int*)d_in[2];
    const float* ea  = (const float*)d_in[3];
    const float* te  = (const float*)d_in[4];
    const float* W1  = (const float*)d_in[5];
    const float* b1  = (const float*)d_in[6];
    const float* W2  = (const float*)d_in[7];
    const float* b2  = (const float*)d_in[8];
    const float* We  = (const float*)d_in[9];
    const float* be  = (const float*)d_in[10];
    const float* Wm1 = (const float*)d_in[11];
    const float* bm1 = (const float*)d_in[12];
    const float* Wm2 = (const float*)d_in[13];
    const float* bm2 = (const float*)d_in[14];
    float* out = (float*)d_out;

    int N = in_sizes[0] / 64;
    int E = in_sizes[1];

    static bool attrs_set = false;
    if (!attrs_set) {
        cudaFuncSetAttribute(node_kernel,
                             cudaFuncAttributeMaxDynamicSharedMemorySize,
                             NODE_SMEM_BYTES);
        cudaFuncSetAttribute(edge_kernel,
                             cudaFuncAttributeMaxDynamicSharedMemorySize,
                             EDGE_SMEM_BYTES);
        attrs_set = true;
    }

    prep_kernel<<<2, 256>>>(We, be, Wm1, bm1, W1, W2);
    node_kernel<<<(N + 127) / 128, 128, NODE_SMEM_BYTES>>>(x, b1, b2, N);
    edge_kernel<<<(E + 127) / 128, 128, EDGE_SMEM_BYTES>>>(ea, te, src, dst,
                                                           Wm2, bm2, out, E);
}

// round 14
// speedup vs baseline: 4.0816x; 1.2358x over previous
#include <cuda_runtime.h>
#include <cuda_fp16.h>
#include <cstdint>

// ----------------------------------------------------------------------------
// TGAT edge classifier.
//   prep (2 blocks): Wz = [We @ Wm1[128:192] ; Wm1[192:224]], bc, bf16 hi/lo
//     mma.sync B fragments for Wz, W1, W2, A1, A2.
//   node: 4 chained 64x64 GEMMs per 128-row block via mma.sync bf16x2-split;
//     cooperative coalesced x staging, then warp-local pipeline; p/q stored
//     as fp16.
//   edge: cooperative coalesced z staging + cp.async-prefetched fp16 p/q
//     gather overlapped with mma.sync bf16x2-split z @ Wz; epilogue
//     relu(.)·Wm2.  3 CTAs/SM.
// ----------------------------------------------------------------------------

#define N_CAP 100000
#define H 64

typedef unsigned long long u64;
typedef uint32_t u32;

__device__ u32 g_p[N_CAP * 32];   // fp16 p table: [n][32] half2-packed
__device__ u32 g_q[N_CAP * 32];   // fp16 q table
__device__ float g_Wz[H * H];     // [k][n] fp32
__device__ float g_bc[H];
__device__ __align__(16) u32 g_Bfh[2048];      // edge Wz fragments hi
__device__ __align__(16) u32 g_Bfl[2048];      // edge Wz fragments lo
__device__ __align__(16) u32 g_Fh[4][2048];    // node W1,W2,A1,A2 frags hi
__device__ __align__(16) u32 g_Fl[4][2048];    // node frags lo

// ---------------------------------------------------------- PTX helpers -----
__device__ __forceinline__ u32 smem_u32(const void* p) {
    u32 a;
    asm("{ .reg .u64 t; cvta.to.shared.u64 t, %1; cvt.u32.u64 %0, t; }"
        : "=r"(a) : "l"(p));
    return a;
}
// bf16x2 = {hi half = bf16(h), lo half = bf16(l)}
__device__ __forceinline__ u32 bf2(float h, float l) {
    u32 r;
    asm("cvt.rn.bf16x2.f32 %0, %1, %2;" : "=r"(r) : "f"(h), "f"(l));
    return r;
}
__device__ __forceinline__ void ldmatrix_x4(u32* r, u32 addr) {
    asm volatile(
        "ldmatrix.sync.aligned.m8n8.x4.shared.b16 {%0,%1,%2,%3}, [%4];"
        : "=r"(r[0]), "=r"(r[1]), "=r"(r[2]), "=r"(r[3]) : "r"(addr));
}
__device__ __forceinline__ void mma_bf16(float* c, const u32* a, const u32* b) {
    asm volatile(
        "mma.sync.aligned.m16n8k16.row.col.f32.bf16.bf16.f32 "
        "{%0,%1,%2,%3}, {%4,%5,%6,%7}, {%8,%9}, {%0,%1,%2,%3};"
        : "+f"(c[0]), "+f"(c[1]), "+f"(c[2]), "+f"(c[3])
        : "r"(a[0]), "r"(a[1]), "r"(a[2]), "r"(a[3]), "r"(b[0]), "r"(b[1]));
}
__device__ __forceinline__ void cp_async16(u32 dst, const void* src) {
    u64 g = (u64)__cvta_generic_to_global(src);
    asm volatile("cp.async.cg.shared.global [%0], [%1], 16;"
                 :: "r"(dst), "l"(g) : "memory");
}
#define CP_COMMIT() asm volatile("cp.async.commit_group;" ::: "memory")
#define CP_WAIT0()  asm volatile("cp.async.wait_group 0;" ::: "memory")

// split a float pair into bf16 hi and lo packed words
__device__ __forceinline__ void split_pair(float v0, float v1, u32& ph, u32& pl) {
    ph = bf2(v1, v0);
    float h0 = __uint_as_float(ph << 16);
    float h1 = __uint_as_float(ph & 0xFFFF0000u);
    pl = bf2(v1 - h1, v0 - h0);
}

// ---------------------------------------------------------------- prep ------
__global__ __launch_bounds__(256) void prep_kernel(
    const float* __restrict__ We, const float* __restrict__ be,
    const float* __restrict__ Wm1, const float* __restrict__ bm1,
    const float* __restrict__ W1, const float* __restrict__ W2) {
    int t = threadIdx.x;

    if (blockIdx.x == 1) {
        const float* mats[4] = {W1, W2, Wm1, Wm1 + 64 * 64};
#pragma unroll
        for (int m = 0; m < 4; ++m) {
            const float* M = mats[m];
            for (int idx = t; idx < 2048; idx += 256) {
                int reg  = idx & 1;
                int lane = (idx >> 1) & 31;
                int tile = idx >> 6;           // kt*8 + nt
                int kt = tile >> 3, nt = tile & 7;
                int g = lane >> 2, tg = lane & 3;
                int n = nt * 8 + g;
                int k0 = kt * 16 + 2 * tg + reg * 8;
                u32 ph, pl;
                split_pair(M[k0 * 64 + n], M[(k0 + 1) * 64 + n], ph, pl);
                g_Fh[m][idx] = ph;
                g_Fl[m][idx] = pl;
            }
        }
        return;
    }

    __shared__ float sWe[2048];
    __shared__ float sA3[4096];

    for (int i = t; i < 512; i += 256)
        reinterpret_cast<float4*>(sWe)[i] = reinterpret_cast<const float4*>(We)[i];
    for (int i = t; i < 1024; i += 256)
        reinterpret_cast<float4*>(sA3)[i] =
            reinterpret_cast<const float4*>(Wm1 + 128 * 64)[i];
    __syncthreads();

#pragma unroll
    for (int u = 0; u < 8; ++u) {
        int idx = u * 256 + t;
        int i = idx >> 6, j = idx & 63;
        float s = 0.f;
#pragma unroll 8
        for (int k = 0; k < 64; ++k)
            s = fmaf(sWe[i * 64 + k], sA3[k * 64 + j], s);
        g_Wz[idx] = s;
    }
    for (int i = t; i < 2048; i += 256)
        g_Wz[2048 + i] = Wm1[192 * 64 + i];
    if (t < 64) {
        float s = bm1[t];
#pragma unroll 8
        for (int k = 0; k < 64; ++k)
            s = fmaf(be[k], sA3[k * 64 + t], s);
        g_bc[t] = s;
    }
    __syncthreads();

    for (int idx = t; idx < 2048; idx += 256) {
        int reg  = idx & 1;
        int lane = (idx >> 1) & 31;
        int tile = idx >> 6;
        int kt = tile >> 3, nt = tile & 7;
        int g = lane >> 2, tg = lane & 3;
        int n = nt * 8 + g;
        int k0 = kt * 16 + 2 * tg + reg * 8;
        u32 ph, pl;
        split_pair(g_Wz[k0 * 64 + n], g_Wz[(k0 + 1) * 64 + n], ph, pl);
        g_Bfh[idx] = ph;
        g_Bfl[idx] = pl;
    }
}

// ------------------------------------------------------------ node stage ----
#define NB_ZH 0
#define NB_ZL 18432
#define NODE_SMEM_BYTES 36864

__device__ __forceinline__ void node_stage_relu(
    char* smc, u32 sb, const u32* Bh, const u32* Bl,
    const float* __restrict__ bias, int wbase, int lane) {
    float acc[2][8][4];
#pragma unroll
    for (int mt = 0; mt < 2; ++mt)
#pragma unroll
        for (int nt = 0; nt < 8; ++nt)
#pragma unroll
            for (int i = 0; i < 4; ++i) acc[mt][nt][i] = 0.f;

    int lrow_off = ((lane >> 3) & 1) * 8 + (lane & 7);
    int lcol = ((lane >> 4) << 3);
#pragma unroll
    for (int kt = 0; kt < 4; ++kt) {
        u32 Ah[2][4], Al[2][4];
#pragma unroll
        for (int mt = 0; mt < 2; ++mt) {
            int row = wbase + mt * 16 + lrow_off;
            u32 off = (u32)(row * 144 + (kt * 16 + lcol) * 2);
            ldmatrix_x4(Ah[mt], sb + NB_ZH + off);
            ldmatrix_x4(Al[mt], sb + NB_ZL + off);
        }
#pragma unroll
        for (int nt = 0; nt < 8; ++nt) {
            int tile = kt * 8 + nt;
            uint2 bh = __ldg(reinterpret_cast<const uint2*>(Bh) + tile * 32 + lane);
            uint2 bl = __ldg(reinterpret_cast<const uint2*>(Bl) + tile * 32 + lane);
            u32 bhv[2] = {bh.x, bh.y};
            u32 blv[2] = {bl.x, bl.y};
#pragma unroll
            for (int mt = 0; mt < 2; ++mt) {
                mma_bf16(acc[mt][nt], Ah[mt], bhv);
                mma_bf16(acc[mt][nt], Ah[mt], blv);
                mma_bf16(acc[mt][nt], Al[mt], bhv);
            }
        }
    }
    __syncwarp();

    int g = lane >> 2, tg = lane & 3;
#pragma unroll
    for (int mt = 0; mt < 2; ++mt) {
        int r0 = wbase + mt * 16 + g;
        int r1 = r0 + 8;
#pragma unroll
        for (int nt = 0; nt < 8; ++nt) {
            int c0 = nt * 8 + 2 * tg;
            float b0 = __ldg(bias + c0), b1v = __ldg(bias + c0 + 1);
            float v0 = fmaxf(acc[mt][nt][0] + b0, 0.f);
            float v1 = fmaxf(acc[mt][nt][1] + b1v, 0.f);
            float v2 = fmaxf(acc[mt][nt][2] + b0, 0.f);
            float v3 = fmaxf(acc[mt][nt][3] + b1v, 0.f);
            u32 ph, pl;
            split_pair(v0, v1, ph, pl);
            *reinterpret_cast<u32*>(smc + NB_ZH + r0 * 144 + c0 * 2) = ph;
            *reinterpret_cast<u32*>(smc + NB_ZL + r0 * 144 + c0 * 2) = pl;
            split_pair(v2, v3, ph, pl);
            *reinterpret_cast<u32*>(smc + NB_ZH + r1 * 144 + c0 * 2) = ph;
            *reinterpret_cast<u32*>(smc + NB_ZL + r1 * 144 + c0 * 2) = pl;
        }
    }
    __syncwarp();
}

// projection stage: out rows = z @ B, stored to gmem as packed fp16
__device__ __forceinline__ void node_stage_proj(
    u32 sb, const u32* Bh, const u32* Bl,
    u32* __restrict__ dst, int n0, int N, int wbase, int lane) {
    float acc[2][8][4];
#pragma unroll
    for (int mt = 0; mt < 2; ++mt)
#pragma unroll
        for (int nt = 0; nt < 8; ++nt)
#pragma unroll
            for (int i = 0; i < 4; ++i) acc[mt][nt][i] = 0.f;

    int lrow_off = ((lane >> 3) & 1) * 8 + (lane & 7);
    int lcol = ((lane >> 4) << 3);
#pragma unroll
    for (int kt = 0; kt < 4; ++kt) {
        u32 Ah[2][4], Al[2][4];
#pragma unroll
        for (int mt = 0; mt < 2; ++mt) {
            int row = wbase + mt * 16 + lrow_off;
            u32 off = (u32)(row * 144 + (kt * 16 + lcol) * 2);
            ldmatrix_x4(Ah[mt], sb + NB_ZH + off);
            ldmatrix_x4(Al[mt], sb + NB_ZL + off);
        }
#pragma unroll
        for (int nt = 0; nt < 8; ++nt) {
            int tile = kt * 8 + nt;
            uint2 bh = __ldg(reinterpret_cast<const uint2*>(Bh) + tile * 32 + lane);
            uint2 bl = __ldg(reinterpret_cast<const uint2*>(Bl) + tile * 32 + lane);
            u32 bhv[2] = {bh.x, bh.y};
            u32 blv[2] = {bl.x, bl.y};
#pragma unroll
            for (int mt = 0; mt < 2; ++mt) {
                mma_bf16(acc[mt][nt], Ah[mt], bhv);
                mma_bf16(acc[mt][nt], Ah[mt], blv);
                mma_bf16(acc[mt][nt], Al[mt], bhv);
            }
        }
    }

    int g = lane >> 2, tg = lane & 3;
#pragma unroll
    for (int mt = 0; mt < 2; ++mt) {
        int r0 = wbase + mt * 16 + g;
        int r1 = r0 + 8;
        bool ok0 = (n0 + r0) < N, ok1 = (n0 + r1) < N;
#pragma unroll
        for (int nt = 0; nt < 8; ++nt) {
            int c0 = nt * 8 + 2 * tg;
            if (ok0) {
                __half2 h = __float22half2_rn(
                    make_float2(acc[mt][nt][0], acc[mt][nt][1]));
                dst[(size_t)(n0 + r0) * 32 + (c0 >> 1)] =
                    *reinterpret_cast<u32*>(&h);
            }
            if (ok1) {
                __half2 h = __float22half2_rn(
                    make_float2(acc[mt][nt][2], acc[mt][nt][3]));
                dst[(size_t)(n0 + r1) * 32 + (c0 >> 1)] =
                    *reinterpret_cast<u32*>(&h);
            }
        }
    }
}

__global__ __launch_bounds__(128) void node_kernel(
    const float* __restrict__ x, const float* __restrict__ b1,
    const float* __restrict__ b2, int N) {
    extern __shared__ char smc[];
    u32 sb = smem_u32(smc);
    int t = threadIdx.x;
    int lane = t & 31, wid = t >> 5;
    int wbase = wid * 32;
    int n0 = blockIdx.x * 128;

    // cooperative coalesced x staging: 16 lanes cover one 256B row
#pragma unroll
    for (int it = 0; it < 16; ++it) {
        int id = it * 128 + t;
        int r = id >> 4, s = id & 15;
        float4 v = (n0 + r < N)
            ? __ldcs(reinterpret_cast<const float4*>(x) +
                     (size_t)(n0 + r) * 16 + s)
            : make_float4(0.f, 0.f, 0.f, 0.f);
        u32 h0, l0, h1, l1;
        split_pair(v.x, v.y, h0, l0);
        split_pair(v.z, v.w, h1, l1);
        *reinterpret_cast<uint2*>(smc + NB_ZH + r * 144 + s * 8) =
            make_uint2(h0, h1);
        *reinterpret_cast<uint2*>(smc + NB_ZL + r * 144 + s * 8) =
            make_uint2(l0, l1);
    }
    __syncthreads();

    node_stage_relu(smc, sb, g_Fh[0], g_Fl[0], b1, wbase, lane);
    node_stage_relu(smc, sb, g_Fh[1], g_Fl[1], b2, wbase, lane);
    node_stage_proj(sb, g_Fh[2], g_Fl[2], g_p, n0, N, wbase, lane);
    node_stage_proj(sb, g_Fh[3], g_Fl[3], g_q, n0, N, wbase, lane);
}

// ------------------------------------------------------------ edge stage ----
// smem bytes: BC 0 (256), WM2 256 (256), SRC 512 (512), DST 1024 (512),
//   ZH 1536 (18432), ZL 19968 (18432), PB 38400 (18432: 128 rows x 144B fp16),
//   QB 56832 (18432)  -> total 75264.  3 CTAs/SM.
#define EB_BC   0
#define EB_WM2  256
#define EB_SRC  512
#define EB_DST  1024
#define EB_ZH   1536
#define EB_ZL   19968
#define EB_PB   38400
#define EB_QB   56832
#define EDGE_SMEM_BYTES 75264

__global__ __launch_bounds__(128, 3) void edge_kernel(
    const float* __restrict__ ea, const float* __restrict__ te,
    const int* __restrict__ src, const int* __restrict__ dst,
    const float* __restrict__ Wm2, const float* __restrict__ bm2,
    float* __restrict__ out, int E) {
    extern __shared__ char smc[];
    float* smf = reinterpret_cast<float*>(smc);
    int t = threadIdx.x;
    int lane = t & 31, wid = t >> 5;
    int wbase = wid * 32;
    u32 sb = smem_u32(smc);

    if (t < 64) {
        smf[EB_WM2 / 4 + t] = Wm2[t];
        smf[EB_BC / 4 + t]  = g_bc[t];
    }
    int e0 = blockIdx.x * 128;
    int e = e0 + t;
    reinterpret_cast<int*>(smc + EB_SRC)[t] = (e < E) ? src[e] : 0;
    reinterpret_cast<int*>(smc + EB_DST)[t] = (e < E) ? dst[e] : 0;
    __syncthreads();

    // cooperative cp.async gather of fp16 p/q rows (128B per row, 8 segs);
    // overlaps z staging + the whole MMA phase below.
    {
        const int* ss = reinterpret_cast<const int*>(smc + EB_SRC);
        const int* dd = reinterpret_cast<const int*>(smc + EB_DST);
#pragma unroll
        for (int it = 0; it < 8; ++it) {
            int id = it * 128 + t;
            int r = id >> 3, s = id & 7;
            u32 soff = (u32)(r * 144 + s * 16);
            cp_async16(sb + EB_PB + soff,
                       reinterpret_cast<const char*>(g_p) +
                           (size_t)ss[r] * 128 + s * 16);
            cp_async16(sb + EB_QB + soff,
                       reinterpret_cast<const char*>(g_q) +
                           (size_t)dd[r] * 128 + s * 16);
        }
        CP_COMMIT();
    }

    // cooperative coalesced z staging: 8 lanes cover one 128B ea/te row;
    // loader converts to bf16 hi/lo and writes the (row,seg) slot directly.
#pragma unroll
    for (int it = 0; it < 8; ++it) {
        int id = it * 128 + t;
        int r = id >> 3, s = id & 7;
        bool ok = (e0 + r) < E;
        float4 v = ok
            ? __ldcs(reinterpret_cast<const float4*>(ea) +
                     (size_t)(e0 + r) * 8 + s)
            : make_float4(0.f, 0.f, 0.f, 0.f);
        u32 h0, l0, h1, l1;
        split_pair(v.x, v.y, h0, l0);
        split_pair(v.z, v.w, h1, l1);
        *reinterpret_cast<uint2*>(smc + EB_ZH + r * 144 + s * 8) =
            make_uint2(h0, h1);
        *reinterpret_cast<uint2*>(smc + EB_ZL + r * 144 + s * 8) =
            make_uint2(l0, l1);
        float4 u = ok
            ? __ldcs(reinterpret_cast<const float4*>(te) +
                     (size_t)(e0 + r) * 8 + s)
            : make_float4(0.f, 0.f, 0.f, 0.f);
        split_pair(u.x, u.y, h0, l0);
        split_pair(u.z, u.w, h1, l1);
        *reinterpret_cast<uint2*>(smc + EB_ZH + r * 144 + 64 + s * 8) =
            make_uint2(h0, h1);
        *reinterpret_cast<uint2*>(smc + EB_ZL + r * 144 + 64 + s * 8) =
            make_uint2(l0, l1);
    }
    __syncthreads();

    // MMA phase (B fragments via __ldg, L1-resident)
    float acc[2][8][4];
#pragma unroll
    for (int mt = 0; mt < 2; ++mt)
#pragma unroll
        for (int nt = 0; nt < 8; ++nt)
#pragma unroll
            for (int i = 0; i < 4; ++i) acc[mt][nt][i] = 0.f;

    {
        int lrow_off = ((lane >> 3) & 1) * 8 + (lane & 7);
        int lcol = ((lane >> 4) << 3);
#pragma unroll
        for (int kt = 0; kt < 4; ++kt) {
            u32 Ah[2][4], Al[2][4];
#pragma unroll
            for (int mt = 0; mt < 2; ++mt) {
                int row = wbase + mt * 16 + lrow_off;
                u32 byteoff = (u32)(row * 144 + (kt * 16 + lcol) * 2);
                ldmatrix_x4(Ah[mt], sb + EB_ZH + byteoff);
                ldmatrix_x4(Al[mt], sb + EB_ZL + byteoff);
            }
#pragma unroll
            for (int nt = 0; nt < 8; ++nt) {
                int tile = kt * 8 + nt;
                uint2 bh = __ldg(reinterpret_cast<const uint2*>(g_Bfh) +
                                 tile * 32 + lane);
                uint2 bl = __ldg(reinterpret_cast<const uint2*>(g_Bfl) +
                                 tile * 32 + lane);
                u32 bhv[2] = {bh.x, bh.y};
                u32 blv[2] = {bl.x, bl.y};
#pragma unroll
                for (int mt = 0; mt < 2; ++mt) {
                    mma_bf16(acc[mt][nt], Ah[mt], bhv);
                    mma_bf16(acc[mt][nt], Ah[mt], blv);
                    mma_bf16(acc[mt][nt], Al[mt], bhv);
                }
            }
        }
    }

    // wait for gathered p/q (should already be resident), then epilogue
    CP_WAIT0();
    __syncthreads();

    {
        const float* bcp = smf + EB_BC / 4;
        const float* wms = smf + EB_WM2 / 4;
        int g = lane >> 2, tg = lane & 3;
        float bm2v = __ldg(bm2);
#pragma unroll
        for (int mt = 0; mt < 2; ++mt) {
            int r0 = wbase + mt * 16 + g;
            int r1 = r0 + 8;
            float sum0 = 0.f, sum1 = 0.f;
#pragma unroll
            for (int nt = 0; nt < 8; ++nt) {
                int c0 = nt * 8 + 2 * tg;
                float2 w   = *reinterpret_cast<const float2*>(wms + c0);
                float2 bc2 = *reinterpret_cast<const float2*>(bcp + c0);
                float2 p0 = __half22float2(*reinterpret_cast<const __half2*>(
                    smc + EB_PB + r0 * 144 + c0 * 2));
                float2 q0 = __half22float2(*reinterpret_cast<const __half2*>(
                    smc + EB_QB + r0 * 144 + c0 * 2));
                float2 p1 = __half22float2(*reinterpret_cast<const __half2*>(
                    smc + EB_PB + r1 * 144 + c0 * 2));
                float2 q1 = __half22float2(*reinterpret_cast<const __half2*>(
                    smc + EB_QB + r1 * 144 + c0 * 2));
                sum0 = fmaf(fmaxf(acc[mt][nt][0] + p0.x + q0.x + bc2.x, 0.f), w.x, sum0);
                sum0 = fmaf(fmaxf(acc[mt][nt][1] + p0.y + q0.y + bc2.y, 0.f), w.y, sum0);
                sum1 = fmaf(fmaxf(acc[mt][nt][2] + p1.x + q1.x + bc2.x, 0.f), w.x, sum1);
                sum1 = fmaf(fmaxf(acc[mt][nt][3] + p1.y + q1.y + bc2.y, 0.f), w.y, sum1);
            }
            sum0 += __shfl_xor_sync(0xFFFFFFFFu, sum0, 1);
            sum0 += __shfl_xor_sync(0xFFFFFFFFu, sum0, 2);
            sum1 += __shfl_xor_sync(0xFFFFFFFFu, sum1, 1);
            sum1 += __shfl_xor_sync(0xFFFFFFFFu, sum1, 2);
            if (tg == 0) {
                if (e0 + r0 < E) out[e0 + r0] = sum0 + bm2v;
                if (e0 + r1 < E) out[e0 + r1] = sum1 + bm2v;
            }
        }
    }
}

// ------------------------------------------------------------ launch --------
extern "C" void kernel_launch(void* const* d_in, const int* in_sizes, int n_in,
                              void* d_out, int out_size) {
    const float* x   = (const float*)d_in[0];
    const int*   src = (const int*)d_in[1];
    const int*   dst = (const int*)d_in[2];
    const float* ea  = (const float*)d_in[3];
    const float* te  = (const float*)d_in[4];
    const float* W1  = (const float*)d_in[5];
    const float* b1  = (const float*)d_in[6];
    const float* W2  = (const float*)d_in[7];
    const float* b2  = (const float*)d_in[8];
    const float* We  = (const float*)d_in[9];
    const float* be  = (const float*)d_in[10];
    const float* Wm1 = (const float*)d_in[11];
    const float* bm1 = (const float*)d_in[12];
    const float* Wm2 = (const float*)d_in[13];
    const float* bm2 = (const float*)d_in[14];
    float* out = (float*)d_out;

    int N = in_sizes[0] / 64;
    int E = in_sizes[1];

    static bool attrs_set = false;
    if (!attrs_set) {
        cudaFuncSetAttribute(node_kernel,
                             cudaFuncAttributeMaxDynamicSharedMemorySize,
                             NODE_SMEM_BYTES);
        cudaFuncSetAttribute(edge_kernel,
                             cudaFuncAttributeMaxDynamicSharedMemorySize,
                             EDGE_SMEM_BYTES);
        attrs_set = true;
    }

    prep_kernel<<<2, 256>>>(We, be, Wm1, bm1, W1, W2);
    node_kernel<<<(N + 127) / 128, 128, NODE_SMEM_BYTES>>>(x, b1, b2, N);
    edge_kernel<<<(E + 127) / 128, 128, EDGE_SMEM_BYTES>>>(ea, te, src, dst,
                                                           Wm2, bm2, out, E);
}